// round 12
// baseline (speedup 1.0000x reference)
#include <cuda_runtime.h>
#include <cuda_fp16.h>
#include <cstdint>
#include <math.h>

#define Ssz 1024
#define Bsz 4
#define Esz 1024
#define SBE (Ssz * Bsz * Esz)
#define GK  2048                    // 2 planes x 1024 (plain fp16)
#define NCHUNK (GK / 64)            // 32 chunks of 64

// ---------------- scratch -----------------------------------------------------
__device__ __align__(16) __half g_Aproj[4096u * GK];
__device__ __align__(16) __half g_Bproj[10240u * GK];
__device__ __align__(16) __half g_Bout [2048u * GK];
__device__ __align__(16) __half g_Aatt [4096u * GK];
__device__ __align__(16) __half g_qp[64u * 1024 * 256]; // [bh][s][qr(128)|qi(128)]
__device__ __align__(16) __half g_kp[64u * 1024 * 256]; // [bh][t][kr|ki]
__device__ __align__(16) __half g_vt[64u * 128 * 1024]; // [bh][vr(64)|vi(64) planes][t]

// ---------------- helpers ------------------------------------------------------
__device__ __forceinline__ uint32_t smem_u32(const void* p) {
    uint32_t a;
    asm("{ .reg .u64 t; cvta.to.shared.u64 t, %1; cvt.u32.u64 %0, t; }" : "=r"(a) : "l"(p));
    return a;
}
__device__ __forceinline__ void cp_async16(uint32_t dst, const void* src) {
    asm volatile("cp.async.cg.shared.global [%0], [%1], 16;" :: "r"(dst), "l"(src) : "memory");
}
#define CP_COMMIT() asm volatile("cp.async.commit_group;" ::: "memory")
#define CP_WAIT0()  asm volatile("cp.async.wait_group 0;" ::: "memory")
#define CP_WAIT1()  asm volatile("cp.async.wait_group 1;" ::: "memory")

__device__ __forceinline__ void ldsm_x4(uint32_t& r0, uint32_t& r1,
                                        uint32_t& r2, uint32_t& r3, uint32_t a) {
    asm volatile("ldmatrix.sync.aligned.m8n8.x4.shared.b16 {%0,%1,%2,%3}, [%4];"
                 : "=r"(r0), "=r"(r1), "=r"(r2), "=r"(r3) : "r"(a));
}
__device__ __forceinline__ void mma_f16(float* d, const uint32_t* a,
                                        uint32_t b0, uint32_t b1) {
    asm volatile(
        "mma.sync.aligned.m16n8k16.row.col.f32.f16.f16.f32 "
        "{%0,%1,%2,%3}, {%4,%5,%6,%7}, {%8,%9}, {%0,%1,%2,%3};"
        : "+f"(d[0]), "+f"(d[1]), "+f"(d[2]), "+f"(d[3])
        : "r"(a[0]), "r"(a[1]), "r"(a[2]), "r"(a[3]), "r"(b0), "r"(b1));
}
__device__ __forceinline__ uint32_t pack_h2(float lo, float hi) {
    uint32_t r;
    asm("cvt.rn.f16x2.f32 %0, %1, %2;" : "=r"(r) : "f"(hi), "f"(lo));
    return r;
}
// e^x for x <= ~0, FMA-pipe only (no MUFU)
__device__ __forceinline__ float fexp(float x) {
    float t = fmaxf(x * 1.4426950408889634f, -126.0f);
    int k = __float2int_rn(t);
    float f = (t - (float)k) * 0.6931471805599453f;
    float p = 1.0f + f * (1.0f + f * (0.5f + f * (0.16666667f +
                   f * (0.041666667f + f * 0.0083333333f))));
    return p * __int_as_float((k + 127) << 23);
}
// sqrt(re^2+im^2) via bit-hack rsqrt + 2 Newton iters (no MUFU)
__device__ __forceinline__ float famp(float re, float im) {
    float z = fmaf(re, re, im * im);
    z = fmaxf(z, 1e-37f);
    float r = __int_as_float(0x5f3759df - (__float_as_int(z) >> 1));
    r = r * fmaf(-0.5f * z * r, r, 1.5f);
    r = r * fmaf(-0.5f * z * r, r, 1.5f);
    return z * r;
}

// ---------------- pack kernels --------------------------------------------------
__global__ __launch_bounds__(256) void pack_A_proj(
    const float* __restrict__ xre, const float* __restrict__ xim)
{
    int idx = blockIdx.x * 256 + threadIdx.x;
    int r = idx >> 10, e = idx & 1023;
    __half* p = g_Aproj + (size_t)r * GK + e;
    p[0] = __float2half(xre[idx]);
    p[1024] = __float2half(xim[idx]);
}

// B rows: real out = [wr, -wi]; imag out = [wi, wr]
__device__ __forceinline__ void write_B_rows(__half* base, size_t n_re,
                                             int e, float wr, float wi)
{
    __half rh = __float2half(wr);
    __half ih = __float2half(wi);
    __half* pr = base + n_re * GK + e;
    pr[0] = rh; pr[1024] = __hneg(ih);
    __half* pi = base + (n_re + 1) * GK + e;
    pi[0] = ih; pi[1024] = rh;
}

__global__ __launch_bounds__(256) void pack_B_proj(
    const float* __restrict__ wq_re, const float* __restrict__ wq_im,
    const float* __restrict__ wk_re, const float* __restrict__ wk_im,
    const float* __restrict__ wv_re, const float* __restrict__ wv_im)
{
    int idx = blockIdx.x * 256 + threadIdx.x;
    int c = idx >> 10, e = idx & 1023;
    const float *wre, *wim; size_t off;
    if (c < 2048)      { wre = wq_re; wim = wq_im; off = (size_t)c * 1024 + e; }
    else if (c < 4096) { wre = wk_re; wim = wk_im; off = (size_t)(c - 2048) * 1024 + e; }
    else               { wre = wv_re; wim = wv_im; off = (size_t)(c - 4096) * 1024 + e; }
    write_B_rows(g_Bproj, (size_t)(2 * c), e, wre[off], wim[off]);
}

__global__ __launch_bounds__(256) void pack_B_out(
    const float* __restrict__ wo_re, const float* __restrict__ wo_im)
{
    int idx = blockIdx.x * 256 + threadIdx.x;
    int f = idx >> 10, e = idx & 1023;
    write_B_rows(g_Bout, (size_t)(2 * f), e,
                 wo_re[(size_t)e * 1024 + f], wo_im[(size_t)e * 1024 + f]);
}

// ---------------- HMMA GEMM (128x128 tile, K-chunk 64, 2 stages, 256 thr, 2 CTA/SM)
#define ROWB   144                  // 64 fp16 = 128B data + 16B pad (conflict-free)
#define STAGEB (256 * ROWB)         // 36864: A(128 rows) + B(128 rows)
#define BOFF   (128 * ROWB)

__device__ __forceinline__ void load_stage(
    uint32_t smb, int stage, const __half* A, const __half* B,
    int rowBase, int colBase, int kk, int tid)
{
    uint32_t base = smb + stage * STAGEB;
#pragma unroll
    for (int i = 0; i < 4; ++i) {   // A: 128 rows x 8 segs
        int v = tid + i * 256, row = v >> 3, seg = v & 7;
        cp_async16(base + row * ROWB + seg * 16,
                   A + (size_t)(rowBase + row) * GK + kk + seg * 8);
    }
#pragma unroll
    for (int i = 0; i < 4; ++i) {   // B: 128 rows x 8 segs
        int v = tid + i * 256, row = v >> 3, seg = v & 7;
        cp_async16(base + BOFF + row * ROWB + seg * 16,
                   B + (size_t)(colBase + row) * GK + kk + seg * 8);
    }
}

__global__ __launch_bounds__(256, 2) void gemm_hmma(
    int mode, float* __restrict__ Dout,
    const float* __restrict__ xre, const float* __restrict__ xim)
{
    extern __shared__ char sm[];
    const uint32_t smb = smem_u32(sm);
    const int tid = threadIdx.x;
    const int wid = tid >> 5, lane = tid & 31;
    const int warpM = wid >> 1, warpN = wid & 1;      // 4 x 2 warps, warp tile 32x64
    const int rowBase = blockIdx.x * 128;
    const int colBase = blockIdx.y * 128;
    const __half* A = mode ? g_Aatt : g_Aproj;
    const __half* B = mode ? g_Bout : g_Bproj;

    float acc[2][8][4];
#pragma unroll
    for (int i = 0; i < 2; ++i)
#pragma unroll
        for (int j = 0; j < 8; ++j)
#pragma unroll
            for (int k = 0; k < 4; ++k) acc[i][j][k] = 0.f;

    load_stage(smb, 0, A, B, rowBase, colBase, 0, tid);  CP_COMMIT();
    load_stage(smb, 1, A, B, rowBase, colBase, 64, tid); CP_COMMIT();

    const uint32_t aRowAddr = smb + (warpM * 32 + (lane & 15)) * ROWB + (lane >> 4) * 16;
    const uint32_t bRowAddr = smb + BOFF + (warpN * 64 + (lane & 15)) * ROWB + (lane >> 4) * 16;

#pragma unroll 1
    for (int c = 0; c < NCHUNK; ++c) {
        CP_WAIT1();
        __syncthreads();
        const uint32_t stoff = (c & 1) * STAGEB;
#pragma unroll
        for (int ks = 0; ks < 4; ++ks) {
            uint32_t a[2][4], b[4][2];
            // A frags + B half0 (jj=0,1)
#pragma unroll
            for (int i = 0; i < 2; ++i)
                ldsm_x4(a[i][0], a[i][1], a[i][2], a[i][3],
                        aRowAddr + stoff + i * 16 * ROWB + ks * 32);
#pragma unroll
            for (int jj = 0; jj < 2; ++jj) {
                uint32_t r0, r1, r2, r3;
                ldsm_x4(r0, r1, r2, r3, bRowAddr + stoff + jj * 16 * ROWB + ks * 32);
                b[2 * jj][0] = r0; b[2 * jj][1] = r2;
                b[2 * jj + 1][0] = r1; b[2 * jj + 1][1] = r3;
            }
            // MMAs j=0..3 issue while B half1 LDSM (below) fills behind them
#pragma unroll
            for (int j = 0; j < 4; ++j)
#pragma unroll
                for (int i = 0; i < 2; ++i)
                    mma_f16(acc[i][j], a[i], b[j][0], b[j][1]);
            // B half1 (jj=2,3)
#pragma unroll
            for (int jj = 0; jj < 2; ++jj) {
                uint32_t r0, r1, r2, r3;
                ldsm_x4(r0, r1, r2, r3, bRowAddr + stoff + (jj + 2) * 16 * ROWB + ks * 32);
                b[2 * jj][0] = r0; b[2 * jj][1] = r2;
                b[2 * jj + 1][0] = r1; b[2 * jj + 1][1] = r3;
            }
#pragma unroll
            for (int j = 0; j < 4; ++j)
#pragma unroll
                for (int i = 0; i < 2; ++i)
                    mma_f16(acc[i][j + 4], a[i], b[j][0], b[j][1]);
        }
        __syncthreads();            // all warps done reading buf (c&1)
        if (c + 2 < NCHUNK)
            load_stage(smb, c & 1, A, B, rowBase, colBase, (c + 2) * 64, tid);
        CP_COMMIT();
    }

    const int lrow = lane >> 2;
#pragma unroll
    for (int i = 0; i < 2; ++i) {
        int r0 = rowBase + warpM * 32 + i * 16 + lrow;
#pragma unroll
        for (int j = 0; j < 8; ++j) {
            int cc = (colBase + warpN * 64 + j * 8 + (lane & 3) * 2) >> 1;
#pragma unroll
            for (int t = 0; t < 2; ++t) {
                int r = r0 + t * 8;
                float vre = acc[i][j][2 * t], vim = acc[i][j][2 * t + 1];
                if (mode == 0) {
                    int s = r >> 2, bb = r & 3;
                    if (cc < 2048) {
                        int h = cc >> 7, m = cc & 127;
                        __half* d = g_qp + ((size_t)(bb * 16 + h) * 1024 + s) * 256;
                        d[m] = __float2half(vre); d[128 + m] = __float2half(vim);
                    } else if (cc < 4096) {
                        int u = cc - 2048, h = u >> 7, m = u & 127;
                        __half* d = g_kp + ((size_t)(bb * 16 + h) * 1024 + s) * 256;
                        d[m] = __float2half(vre); d[128 + m] = __float2half(vim);
                    } else {
                        int u = cc - 4096, h = u >> 6, vc = u & 63;
                        __half* d = g_vt + (size_t)(bb * 16 + h) * 128 * 1024;
                        d[(size_t)vc * 1024 + s]        = __float2half(vre);
                        d[(size_t)(64 + vc) * 1024 + s] = __float2half(vim);
                    }
                } else {
                    size_t i0 = (size_t)r * 1024 + cc;
                    Dout[i0]       = vre + xre[i0];
                    Dout[SBE + i0] = vim + xim[i0];
                }
            }
        }
    }
}

// ---------------- HMMA flash attention (unchanged) -------------------------------
#define QPITCH 528
#define KPITCH 528
#define VPITCH 80
#define AT_SMK0 (64 * QPITCH)
#define AT_SMK1 (AT_SMK0 + 32 * KPITCH)
#define AT_SMV0 (AT_SMK1 + 32 * KPITCH)
#define AT_SMV1 (AT_SMV0 + 128 * VPITCH)
#define AT_TOT  (AT_SMV1 + 128 * VPITCH)

__device__ __forceinline__ void load_kv(uint32_t smb, int buf,
    const __half* Kg, const __half* Vg, int kt, int tid)
{
    uint32_t kdst = smb + (buf ? AT_SMK1 : AT_SMK0);
    const __half* ksrc = Kg + (size_t)kt * 32 * 256;
#pragma unroll
    for (int i = 0; i < 8; ++i) {
        int c = tid + i * 128, row = c >> 5, seg = c & 31;
        cp_async16(kdst + row * KPITCH + seg * 16, ksrc + (size_t)row * 256 + seg * 8);
    }
    uint32_t vdst = smb + (buf ? AT_SMV1 : AT_SMV0);
#pragma unroll
    for (int i = 0; i < 4; ++i) {
        int c = tid + i * 128, vc = c >> 2, seg = c & 3;
        cp_async16(vdst + vc * VPITCH + seg * 16,
                   Vg + (size_t)vc * 1024 + kt * 32 + seg * 8);
    }
}

__global__ __launch_bounds__(128) void attn_mma()
{
    extern __shared__ char sm[];
    const uint32_t smb = smem_u32(sm);
    const int tid = threadIdx.x, lane = tid & 31, wid = tid >> 5;
    const int qt = 15 - blockIdx.x;
    const int bh = blockIdx.y;
    const int qbase = qt * 64;
    const int nkt = 2 * qt + 2;
    const float scale = 0.088388347648318447f;

    const __half* Qg = g_qp + ((size_t)bh * 1024 + qbase) * 256;
    const __half* Kg = g_kp + (size_t)bh * 1024 * 256;
    const __half* Vg = g_vt + (size_t)bh * 128 * 1024;

#pragma unroll
    for (int i = 0; i < 16; ++i) {
        int c = tid + i * 128, row = c >> 5, seg = c & 31;
        cp_async16(smb + row * QPITCH + seg * 16, Qg + (size_t)row * 256 + seg * 8);
    }
    load_kv(smb, 0, Kg, Vg, 0, tid);
    CP_COMMIT();

    float m0 = -1e30f, m1 = -1e30f, l0 = 0.f, l1 = 0.f;
    float accR[8][4], accI[8][4];
#pragma unroll
    for (int j = 0; j < 8; ++j)
#pragma unroll
        for (int k = 0; k < 4; ++k) { accR[j][k] = 0.f; accI[j][k] = 0.f; }

    const int rowg = qbase + wid * 16 + (lane >> 2);
    const uint32_t aBase = smb + (wid * 16 + (lane & 15)) * QPITCH + (lane >> 4) * 16;

#pragma unroll 1
    for (int kt = 0; kt < nkt; ++kt) {
        if (kt + 1 < nkt) { load_kv(smb, (kt + 1) & 1, Kg, Vg, kt + 1, tid); CP_COMMIT(); CP_WAIT1(); }
        else CP_WAIT0();
        __syncthreads();
        const uint32_t kbuf = smb + ((kt & 1) ? AT_SMK1 : AT_SMK0);
        const uint32_t vbuf = smb + ((kt & 1) ? AT_SMV1 : AT_SMV0);

        float S[4][4][4];
#pragma unroll
        for (int c2 = 0; c2 < 4; ++c2)
#pragma unroll
            for (int n = 0; n < 4; ++n)
#pragma unroll
                for (int q = 0; q < 4; ++q) S[c2][n][q] = 0.f;

#pragma unroll
        for (int ks = 0; ks < 8; ++ks) {
            uint32_t ar[4], ai[4];
            uint32_t aa = aBase + ks * 32;
            ldsm_x4(ar[0], ar[1], ar[2], ar[3], aa);
            ldsm_x4(ai[0], ai[1], ai[2], ai[3], aa + 256);
#pragma unroll
            for (int ntp = 0; ntp < 2; ++ntp) {
                uint32_t ba = kbuf + (ntp * 16 + (lane & 15)) * KPITCH + (lane >> 4) * 16 + ks * 32;
                uint32_t br[4], bi[4];
                ldsm_x4(br[0], br[1], br[2], br[3], ba);
                ldsm_x4(bi[0], bi[1], bi[2], bi[3], ba + 256);
#pragma unroll
                for (int t2 = 0; t2 < 2; ++t2) {
                    int nt = 2 * ntp + t2;
                    mma_f16(S[0][nt], ar, br[t2], br[t2 + 2]);
                    mma_f16(S[1][nt], ai, bi[t2], bi[t2 + 2]);
                    mma_f16(S[2][nt], ar, bi[t2], bi[t2 + 2]);
                    mma_f16(S[3][nt], ai, br[t2], br[t2 + 2]);
                }
            }
        }

        float mx0 = -1e30f, mx1 = -1e30f;
#pragma unroll
        for (int nt = 0; nt < 4; ++nt)
#pragma unroll
            for (int q = 0; q < 4; ++q) {
                float re = S[0][nt][q] - S[1][nt][q];
                float im = S[2][nt][q] + S[3][nt][q];
                float amp = famp(re, im) * scale;
                int col = kt * 32 + nt * 8 + (lane & 3) * 2 + (q & 1);
                int row = rowg + ((q >> 1) ? 8 : 0);
                float logit = (col <= row) ? amp : -1e30f;
                S[0][nt][q] = logit;
                if (q < 2) mx0 = fmaxf(mx0, logit);
                else       mx1 = fmaxf(mx1, logit);
            }
        mx0 = fmaxf(mx0, __shfl_xor_sync(~0u, mx0, 1));
        mx0 = fmaxf(mx0, __shfl_xor_sync(~0u, mx0, 2));
        mx1 = fmaxf(mx1, __shfl_xor_sync(~0u, mx1, 1));
        mx1 = fmaxf(mx1, __shfl_xor_sync(~0u, mx1, 2));
        float m0n = fmaxf(m0, mx0), m1n = fmaxf(m1, mx1);
        float corr0 = fexp(m0 - m0n), corr1 = fexp(m1 - m1n);
        float ph[4][4];
        float sum0 = 0.f, sum1 = 0.f;
#pragma unroll
        for (int nt = 0; nt < 4; ++nt)
#pragma unroll
            for (int q = 0; q < 4; ++q) {
                float p = fexp(S[0][nt][q] - ((q < 2) ? m0n : m1n));
                if (q < 2) sum0 += p; else sum1 += p;
                ph[nt][q] = p;
            }
        sum0 += __shfl_xor_sync(~0u, sum0, 1);
        sum0 += __shfl_xor_sync(~0u, sum0, 2);
        sum1 += __shfl_xor_sync(~0u, sum1, 1);
        sum1 += __shfl_xor_sync(~0u, sum1, 2);
        l0 = l0 * corr0 + sum0;
        l1 = l1 * corr1 + sum1;
        m0 = m0n; m1 = m1n;
#pragma unroll
        for (int j = 0; j < 8; ++j) {
            accR[j][0] *= corr0; accR[j][1] *= corr0;
            accR[j][2] *= corr1; accR[j][3] *= corr1;
            accI[j][0] *= corr0; accI[j][1] *= corr0;
            accI[j][2] *= corr1; accI[j][3] *= corr1;
        }

#pragma unroll
        for (int s = 0; s < 2; ++s) {
            uint32_t Ah[4];
            Ah[0] = pack_h2(ph[2 * s][0], ph[2 * s][1]);
            Ah[1] = pack_h2(ph[2 * s][2], ph[2 * s][3]);
            Ah[2] = pack_h2(ph[2 * s + 1][0], ph[2 * s + 1][1]);
            Ah[3] = pack_h2(ph[2 * s + 1][2], ph[2 * s + 1][3]);
#pragma unroll
            for (int pr = 0; pr < 4; ++pr) {
                uint32_t va = vbuf + (pr * 16 + (lane & 15)) * VPITCH + (lane >> 4) * 16 + s * 32;
                uint32_t vr[4], vi[4];
                ldsm_x4(vr[0], vr[1], vr[2], vr[3], va);
                ldsm_x4(vi[0], vi[1], vi[2], vi[3], va + 64 * VPITCH);
                mma_f16(accR[2 * pr],     Ah, vr[0], vr[2]);
                mma_f16(accR[2 * pr + 1], Ah, vr[1], vr[3]);
                mma_f16(accI[2 * pr],     Ah, vi[0], vi[2]);
                mma_f16(accI[2 * pr + 1], Ah, vi[1], vi[3]);
            }
        }
        __syncthreads();
    }

    const float inv0 = 1.0f / l0, inv1 = 1.0f / l1;
    const int b = bh >> 4, h = bh & 15;
#pragma unroll
    for (int t = 0; t < 2; ++t) {
        int srow = rowg + t * 8;
        size_t r = (size_t)srow * 4 + b;
        float inv = t ? inv1 : inv0;
#pragma unroll
        for (int j = 0; j < 8; ++j)
#pragma unroll
            for (int e2 = 0; e2 < 2; ++e2) {
                int vc = j * 8 + (lane & 3) * 2 + e2;
                float re = accR[j][2 * t + e2] * inv;
                float im = accI[j][2 * t + e2] * inv;
                __half* p = g_Aatt + r * GK + (h * 64 + vc);
                p[0] = __float2half(re);
                p[1024] = __float2half(im);
            }
    }
}

// ---------------------------------------------------------------------------
extern "C" void kernel_launch(void* const* d_in, const int* in_sizes, int n_in,
                              void* d_out, int out_size)
{
    const float* xre = (const float*)d_in[0];
    const float* xim = (const float*)d_in[1];
    float* out = (float*)d_out;

    const int gemm_smem = 2 * STAGEB;                 // 73728 per CTA (2 CTAs/SM)
    static bool attr_set = false;
    if (!attr_set) {
        cudaFuncSetAttribute(gemm_hmma,
                             cudaFuncAttributeMaxDynamicSharedMemorySize, gemm_smem);
        cudaFuncSetAttribute(attn_mma,
                             cudaFuncAttributeMaxDynamicSharedMemorySize, AT_TOT);
        attr_set = true;
    }

    pack_A_proj<<<16384, 256>>>(xre, xim);
    pack_B_proj<<<20480, 256>>>((const float*)d_in[2], (const float*)d_in[3],
                                (const float*)d_in[4], (const float*)d_in[5],
                                (const float*)d_in[6], (const float*)d_in[7]);
    pack_B_out<<<4096, 256>>>((const float*)d_in[8], (const float*)d_in[9]);

    gemm_hmma<<<dim3(32, 80), 256, gemm_smem>>>(0, nullptr, nullptr, nullptr);

    attn_mma<<<dim3(16, 64), 128, AT_TOT>>>();

    gemm_hmma<<<dim3(32, 16), 256, gemm_smem>>>(1, out, xre, xim);
}

// round 13
// speedup vs baseline: 1.0223x; 1.0223x over previous
#include <cuda_runtime.h>
#include <cuda_fp16.h>
#include <cstdint>
#include <math.h>

#define Ssz 1024
#define Bsz 4
#define Esz 1024
#define SBE (Ssz * Bsz * Esz)
#define GK  3072                    // 3 planes x 1024 (Gauss: ar | ai | ar+ai)
#define NCHUNK 48                   // 48 chunks of 64 (16 per product phase)

// ---------------- scratch -----------------------------------------------------
__device__ __align__(16) __half g_Aproj[4096u * GK];
__device__ __align__(16) __half g_Bproj[5120u * GK];
__device__ __align__(16) __half g_Bout [1024u * GK];
__device__ __align__(16) __half g_Aatt [4096u * GK];
__device__ __align__(16) __half g_qp[64u * 1024 * 256]; // [bh][s][qr(128)|qi(128)]
__device__ __align__(16) __half g_kp[64u * 1024 * 256]; // [bh][t][kr|ki]
__device__ __align__(16) __half g_vt[64u * 128 * 1024]; // [bh][vr(64)|vi(64) planes][t]

// ---------------- helpers ------------------------------------------------------
__device__ __forceinline__ uint32_t smem_u32(const void* p) {
    uint32_t a;
    asm("{ .reg .u64 t; cvta.to.shared.u64 t, %1; cvt.u32.u64 %0, t; }" : "=r"(a) : "l"(p));
    return a;
}
__device__ __forceinline__ void cp_async16(uint32_t dst, const void* src) {
    asm volatile("cp.async.cg.shared.global [%0], [%1], 16;" :: "r"(dst), "l"(src) : "memory");
}
#define CP_COMMIT() asm volatile("cp.async.commit_group;" ::: "memory")
#define CP_WAIT0()  asm volatile("cp.async.wait_group 0;" ::: "memory")
#define CP_WAIT1()  asm volatile("cp.async.wait_group 1;" ::: "memory")

__device__ __forceinline__ void ldsm_x4(uint32_t& r0, uint32_t& r1,
                                        uint32_t& r2, uint32_t& r3, uint32_t a) {
    asm volatile("ldmatrix.sync.aligned.m8n8.x4.shared.b16 {%0,%1,%2,%3}, [%4];"
                 : "=r"(r0), "=r"(r1), "=r"(r2), "=r"(r3) : "r"(a));
}
__device__ __forceinline__ void mma_f16(float* d, const uint32_t* a,
                                        uint32_t b0, uint32_t b1) {
    asm volatile(
        "mma.sync.aligned.m16n8k16.row.col.f32.f16.f16.f32 "
        "{%0,%1,%2,%3}, {%4,%5,%6,%7}, {%8,%9}, {%0,%1,%2,%3};"
        : "+f"(d[0]), "+f"(d[1]), "+f"(d[2]), "+f"(d[3])
        : "r"(a[0]), "r"(a[1]), "r"(a[2]), "r"(a[3]), "r"(b0), "r"(b1));
}
__device__ __forceinline__ uint32_t pack_h2(float lo, float hi) {
    uint32_t r;
    asm("cvt.rn.f16x2.f32 %0, %1, %2;" : "=r"(r) : "f"(hi), "f"(lo));
    return r;
}
// e^x for x <= ~0, FMA-pipe only (no MUFU)
__device__ __forceinline__ float fexp(float x) {
    float t = fmaxf(x * 1.4426950408889634f, -126.0f);
    int k = __float2int_rn(t);
    float f = (t - (float)k) * 0.6931471805599453f;
    float p = 1.0f + f * (1.0f + f * (0.5f + f * (0.16666667f +
                   f * (0.041666667f + f * 0.0083333333f))));
    return p * __int_as_float((k + 127) << 23);
}
// sqrt(re^2+im^2) via bit-hack rsqrt + 2 Newton iters (no MUFU)
__device__ __forceinline__ float famp(float re, float im) {
    float z = fmaf(re, re, im * im);
    z = fmaxf(z, 1e-37f);
    float r = __int_as_float(0x5f3759df - (__float_as_int(z) >> 1));
    r = r * fmaf(-0.5f * z * r, r, 1.5f);
    r = r * fmaf(-0.5f * z * r, r, 1.5f);
    return z * r;
}

// ---------------- pack kernels --------------------------------------------------
__global__ __launch_bounds__(256) void pack_A_proj(
    const float* __restrict__ xre, const float* __restrict__ xim)
{
    int idx = blockIdx.x * 256 + threadIdx.x;
    int r = idx >> 10, e = idx & 1023;
    float ar = xre[idx], ai = xim[idx];
    __half* p = g_Aproj + (size_t)r * GK + e;
    p[0] = __float2half(ar);
    p[1024] = __float2half(ai);
    p[2048] = __float2half(ar + ai);
}

// Gauss B row: [br | bi | br+bi]
__device__ __forceinline__ void write_B_row(__half* base, size_t row,
                                            int e, float wr, float wi)
{
    __half* p = base + row * GK + e;
    p[0] = __float2half(wr);
    p[1024] = __float2half(wi);
    p[2048] = __float2half(wr + wi);
}

__global__ __launch_bounds__(256) void pack_B_proj(
    const float* __restrict__ wq_re, const float* __restrict__ wq_im,
    const float* __restrict__ wk_re, const float* __restrict__ wk_im,
    const float* __restrict__ wv_re, const float* __restrict__ wv_im)
{
    int idx = blockIdx.x * 256 + threadIdx.x;
    int c = idx >> 10, e = idx & 1023;
    const float *wre, *wim; size_t off;
    if (c < 2048)      { wre = wq_re; wim = wq_im; off = (size_t)c * 1024 + e; }
    else if (c < 4096) { wre = wk_re; wim = wk_im; off = (size_t)(c - 2048) * 1024 + e; }
    else               { wre = wv_re; wim = wv_im; off = (size_t)(c - 4096) * 1024 + e; }
    write_B_row(g_Bproj, (size_t)c, e, wre[off], wim[off]);
}

__global__ __launch_bounds__(256) void pack_B_out(
    const float* __restrict__ wo_re, const float* __restrict__ wo_im)
{
    int idx = blockIdx.x * 256 + threadIdx.x;
    int f = idx >> 10, e = idx & 1023;
    write_B_row(g_Bout, (size_t)f, e,
                wo_re[(size_t)e * 1024 + f], wo_im[(size_t)e * 1024 + f]);
}

// ------ Gauss HMMA GEMM (128 rows x 64 complex cols, K-chunk 64, 2 CTA/SM) -----
#define ROWB   144                  // 64 fp16 = 128B data + 16B pad
#define STAGEB (192 * ROWB)         // 27648: A(128 rows) + B(64 rows)
#define BOFF   (128 * ROWB)

__device__ __forceinline__ void load_stage(
    uint32_t smb, int stage, const __half* A, const __half* B,
    int rowBase, int colBase, int kk, int tid)
{
    uint32_t base = smb + stage * STAGEB;
#pragma unroll
    for (int i = 0; i < 4; ++i) {   // A: 128 rows x 8 segs
        int v = tid + i * 256, row = v >> 3, seg = v & 7;
        cp_async16(base + row * ROWB + seg * 16,
                   A + (size_t)(rowBase + row) * GK + kk + seg * 8);
    }
#pragma unroll
    for (int i = 0; i < 2; ++i) {   // B: 64 rows x 8 segs
        int v = tid + i * 256, row = v >> 3, seg = v & 7;
        cp_async16(base + BOFF + row * ROWB + seg * 16,
                   B + (size_t)(colBase + row) * GK + kk + seg * 8);
    }
}

__global__ __launch_bounds__(256, 2) void gemm_hmma(
    int mode, float* __restrict__ Dout,
    const float* __restrict__ xre, const float* __restrict__ xim)
{
    extern __shared__ char sm[];
    const uint32_t smb = smem_u32(sm);
    const int tid = threadIdx.x;
    const int wid = tid >> 5, lane = tid & 31;
    const int warpM = wid >> 1, warpN = wid & 1;      // 4M x 2N, warp 32 x 32c
    const int rowBase = blockIdx.x * 128;
    const int colBase = blockIdx.y * 64;              // complex cols
    const __half* A = mode ? g_Aatt : g_Aproj;
    const __half* B = mode ? g_Bout : g_Bproj;

    float accP[3][2][4][4];                           // P1,P2,P3
#pragma unroll
    for (int p = 0; p < 3; ++p)
#pragma unroll
        for (int i = 0; i < 2; ++i)
#pragma unroll
            for (int j = 0; j < 4; ++j)
#pragma unroll
                for (int k = 0; k < 4; ++k) accP[p][i][j][k] = 0.f;

    load_stage(smb, 0, A, B, rowBase, colBase, 0, tid);  CP_COMMIT();
    load_stage(smb, 1, A, B, rowBase, colBase, 64, tid); CP_COMMIT();

    const uint32_t aRowAddr = smb + (warpM * 32 + (lane & 15)) * ROWB + (lane >> 4) * 16;
    const uint32_t bRowAddr = smb + BOFF + (warpN * 32 + (lane & 15)) * ROWB + (lane >> 4) * 16;

#pragma unroll
    for (int ph = 0; ph < 3; ++ph) {
#pragma unroll 1
        for (int c2 = 0; c2 < 16; ++c2) {
            const int c = ph * 16 + c2;
            CP_WAIT1();
            __syncthreads();
            const uint32_t stoff = (c & 1) * STAGEB;
#pragma unroll
            for (int ks = 0; ks < 4; ++ks) {
                uint32_t a[2][4], b[4][2];
#pragma unroll
                for (int i = 0; i < 2; ++i)
                    ldsm_x4(a[i][0], a[i][1], a[i][2], a[i][3],
                            aRowAddr + stoff + i * 16 * ROWB + ks * 32);
#pragma unroll
                for (int jj = 0; jj < 2; ++jj) {
                    uint32_t r0, r1, r2, r3;
                    ldsm_x4(r0, r1, r2, r3, bRowAddr + stoff + jj * 16 * ROWB + ks * 32);
                    b[2 * jj][0] = r0; b[2 * jj][1] = r2;
                    b[2 * jj + 1][0] = r1; b[2 * jj + 1][1] = r3;
                }
#pragma unroll
                for (int i = 0; i < 2; ++i)
#pragma unroll
                    for (int j = 0; j < 4; ++j)
                        mma_f16(accP[ph][i][j], a[i], b[j][0], b[j][1]);
            }
            __syncthreads();
            if (c + 2 < NCHUNK)
                load_stage(smb, c & 1, A, B, rowBase, colBase, (c + 2) * 64, tid);
            CP_COMMIT();
        }
    }

    const int lrow = lane >> 2;
#pragma unroll
    for (int i = 0; i < 2; ++i) {
        int r0 = rowBase + warpM * 32 + i * 16 + lrow;
#pragma unroll
        for (int j = 0; j < 4; ++j) {
            int ccc = colBase + warpN * 32 + j * 8 + (lane & 3) * 2;
#pragma unroll
            for (int t = 0; t < 2; ++t) {
                int r = r0 + t * 8;
#pragma unroll
                for (int e2 = 0; e2 < 2; ++e2) {
                    int q = 2 * t + e2;
                    float P1 = accP[0][i][j][q];
                    float P2 = accP[1][i][j][q];
                    float P3 = accP[2][i][j][q];
                    float vre = P1 - P2;
                    float vim = P3 - P1 - P2;
                    int cc = ccc + e2;
                    if (mode == 0) {
                        int s = r >> 2, bb = r & 3;
                        if (cc < 2048) {
                            int h = cc >> 7, m = cc & 127;
                            __half* d = g_qp + ((size_t)(bb * 16 + h) * 1024 + s) * 256;
                            d[m] = __float2half(vre); d[128 + m] = __float2half(vim);
                        } else if (cc < 4096) {
                            int u = cc - 2048, h = u >> 7, m = u & 127;
                            __half* d = g_kp + ((size_t)(bb * 16 + h) * 1024 + s) * 256;
                            d[m] = __float2half(vre); d[128 + m] = __float2half(vim);
                        } else {
                            int u = cc - 4096, h = u >> 6, vc = u & 63;
                            __half* d = g_vt + (size_t)(bb * 16 + h) * 128 * 1024;
                            d[(size_t)vc * 1024 + s]        = __float2half(vre);
                            d[(size_t)(64 + vc) * 1024 + s] = __float2half(vim);
                        }
                    } else {
                        size_t i0 = (size_t)r * 1024 + cc;
                        Dout[i0]       = vre + xre[i0];
                        Dout[SBE + i0] = vim + xim[i0];
                    }
                }
            }
        }
    }
}

// ---------------- HMMA flash attention (unchanged core) --------------------------
#define QPITCH 528
#define KPITCH 528
#define VPITCH 80
#define AT_SMK0 (64 * QPITCH)
#define AT_SMK1 (AT_SMK0 + 32 * KPITCH)
#define AT_SMV0 (AT_SMK1 + 32 * KPITCH)
#define AT_SMV1 (AT_SMV0 + 128 * VPITCH)
#define AT_TOT  (AT_SMV1 + 128 * VPITCH)

__device__ __forceinline__ void load_kv(uint32_t smb, int buf,
    const __half* Kg, const __half* Vg, int kt, int tid)
{
    uint32_t kdst = smb + (buf ? AT_SMK1 : AT_SMK0);
    const __half* ksrc = Kg + (size_t)kt * 32 * 256;
#pragma unroll
    for (int i = 0; i < 8; ++i) {
        int c = tid + i * 128, row = c >> 5, seg = c & 31;
        cp_async16(kdst + row * KPITCH + seg * 16, ksrc + (size_t)row * 256 + seg * 8);
    }
    uint32_t vdst = smb + (buf ? AT_SMV1 : AT_SMV0);
#pragma unroll
    for (int i = 0; i < 4; ++i) {
        int c = tid + i * 128, vc = c >> 2, seg = c & 3;
        cp_async16(vdst + vc * VPITCH + seg * 16,
                   Vg + (size_t)vc * 1024 + kt * 32 + seg * 8);
    }
}

__global__ __launch_bounds__(128) void attn_mma()
{
    extern __shared__ char sm[];
    const uint32_t smb = smem_u32(sm);
    const int tid = threadIdx.x, lane = tid & 31, wid = tid >> 5;
    const int qt = 15 - blockIdx.x;
    const int bh = blockIdx.y;
    const int qbase = qt * 64;
    const int nkt = 2 * qt + 2;
    const float scale = 0.088388347648318447f;

    const __half* Qg = g_qp + ((size_t)bh * 1024 + qbase) * 256;
    const __half* Kg = g_kp + (size_t)bh * 1024 * 256;
    const __half* Vg = g_vt + (size_t)bh * 128 * 1024;

#pragma unroll
    for (int i = 0; i < 16; ++i) {
        int c = tid + i * 128, row = c >> 5, seg = c & 31;
        cp_async16(smb + row * QPITCH + seg * 16, Qg + (size_t)row * 256 + seg * 8);
    }
    load_kv(smb, 0, Kg, Vg, 0, tid);
    CP_COMMIT();

    float m0 = -1e30f, m1 = -1e30f, l0 = 0.f, l1 = 0.f;
    float accR[8][4], accI[8][4];
#pragma unroll
    for (int j = 0; j < 8; ++j)
#pragma unroll
        for (int k = 0; k < 4; ++k) { accR[j][k] = 0.f; accI[j][k] = 0.f; }

    const int rowg = qbase + wid * 16 + (lane >> 2);
    const uint32_t aBase = smb + (wid * 16 + (lane & 15)) * QPITCH + (lane >> 4) * 16;

#pragma unroll 1
    for (int kt = 0; kt < nkt; ++kt) {
        if (kt + 1 < nkt) { load_kv(smb, (kt + 1) & 1, Kg, Vg, kt + 1, tid); CP_COMMIT(); CP_WAIT1(); }
        else CP_WAIT0();
        __syncthreads();
        const uint32_t kbuf = smb + ((kt & 1) ? AT_SMK1 : AT_SMK0);
        const uint32_t vbuf = smb + ((kt & 1) ? AT_SMV1 : AT_SMV0);

        float S[4][4][4];
#pragma unroll
        for (int c2 = 0; c2 < 4; ++c2)
#pragma unroll
            for (int n = 0; n < 4; ++n)
#pragma unroll
                for (int q = 0; q < 4; ++q) S[c2][n][q] = 0.f;

#pragma unroll
        for (int ks = 0; ks < 8; ++ks) {
            uint32_t ar[4], ai[4];
            uint32_t aa = aBase + ks * 32;
            ldsm_x4(ar[0], ar[1], ar[2], ar[3], aa);
            ldsm_x4(ai[0], ai[1], ai[2], ai[3], aa + 256);
#pragma unroll
            for (int ntp = 0; ntp < 2; ++ntp) {
                uint32_t ba = kbuf + (ntp * 16 + (lane & 15)) * KPITCH + (lane >> 4) * 16 + ks * 32;
                uint32_t br[4], bi[4];
                ldsm_x4(br[0], br[1], br[2], br[3], ba);
                ldsm_x4(bi[0], bi[1], bi[2], bi[3], ba + 256);
#pragma unroll
                for (int t2 = 0; t2 < 2; ++t2) {
                    int nt = 2 * ntp + t2;
                    mma_f16(S[0][nt], ar, br[t2], br[t2 + 2]);
                    mma_f16(S[1][nt], ai, bi[t2], bi[t2 + 2]);
                    mma_f16(S[2][nt], ar, bi[t2], bi[t2 + 2]);
                    mma_f16(S[3][nt], ai, br[t2], br[t2 + 2]);
                }
            }
        }

        float mx0 = -1e30f, mx1 = -1e30f;
#pragma unroll
        for (int nt = 0; nt < 4; ++nt)
#pragma unroll
            for (int q = 0; q < 4; ++q) {
                float re = S[0][nt][q] - S[1][nt][q];
                float im = S[2][nt][q] + S[3][nt][q];
                float amp = famp(re, im) * scale;
                int col = kt * 32 + nt * 8 + (lane & 3) * 2 + (q & 1);
                int row = rowg + ((q >> 1) ? 8 : 0);
                float logit = (col <= row) ? amp : -1e30f;
                S[0][nt][q] = logit;
                if (q < 2) mx0 = fmaxf(mx0, logit);
                else       mx1 = fmaxf(mx1, logit);
            }
        mx0 = fmaxf(mx0, __shfl_xor_sync(~0u, mx0, 1));
        mx0 = fmaxf(mx0, __shfl_xor_sync(~0u, mx0, 2));
        mx1 = fmaxf(mx1, __shfl_xor_sync(~0u, mx1, 1));
        mx1 = fmaxf(mx1, __shfl_xor_sync(~0u, mx1, 2));
        float m0n = fmaxf(m0, mx0), m1n = fmaxf(m1, mx1);
        float corr0 = fexp(m0 - m0n), corr1 = fexp(m1 - m1n);
        float ph[4][4];
        float sum0 = 0.f, sum1 = 0.f;
#pragma unroll
        for (int nt = 0; nt < 4; ++nt)
#pragma unroll
            for (int q = 0; q < 4; ++q) {
                float p = fexp(S[0][nt][q] - ((q < 2) ? m0n : m1n));
                if (q < 2) sum0 += p; else sum1 += p;
                ph[nt][q] = p;
            }
        sum0 += __shfl_xor_sync(~0u, sum0, 1);
        sum0 += __shfl_xor_sync(~0u, sum0, 2);
        sum1 += __shfl_xor_sync(~0u, sum1, 1);
        sum1 += __shfl_xor_sync(~0u, sum1, 2);
        l0 = l0 * corr0 + sum0;
        l1 = l1 * corr1 + sum1;
        m0 = m0n; m1 = m1n;
#pragma unroll
        for (int j = 0; j < 8; ++j) {
            accR[j][0] *= corr0; accR[j][1] *= corr0;
            accR[j][2] *= corr1; accR[j][3] *= corr1;
            accI[j][0] *= corr0; accI[j][1] *= corr0;
            accI[j][2] *= corr1; accI[j][3] *= corr1;
        }

#pragma unroll
        for (int s = 0; s < 2; ++s) {
            uint32_t Ah[4];
            Ah[0] = pack_h2(ph[2 * s][0], ph[2 * s][1]);
            Ah[1] = pack_h2(ph[2 * s][2], ph[2 * s][3]);
            Ah[2] = pack_h2(ph[2 * s + 1][0], ph[2 * s + 1][1]);
            Ah[3] = pack_h2(ph[2 * s + 1][2], ph[2 * s + 1][3]);
#pragma unroll
            for (int pr = 0; pr < 4; ++pr) {
                uint32_t va = vbuf + (pr * 16 + (lane & 15)) * VPITCH + (lane >> 4) * 16 + s * 32;
                uint32_t vr[4], vi[4];
                ldsm_x4(vr[0], vr[1], vr[2], vr[3], va);
                ldsm_x4(vi[0], vi[1], vi[2], vi[3], va + 64 * VPITCH);
                mma_f16(accR[2 * pr],     Ah, vr[0], vr[2]);
                mma_f16(accR[2 * pr + 1], Ah, vr[1], vr[3]);
                mma_f16(accI[2 * pr],     Ah, vi[0], vi[2]);
                mma_f16(accI[2 * pr + 1], Ah, vi[1], vi[3]);
            }
        }
        __syncthreads();
    }

    // epilogue: write Gauss-packed A rows for the out-GEMM
    const float inv0 = 1.0f / l0, inv1 = 1.0f / l1;
    const int b = bh >> 4, h = bh & 15;
#pragma unroll
    for (int t = 0; t < 2; ++t) {
        int srow = rowg + t * 8;
        size_t r = (size_t)srow * 4 + b;
        float inv = t ? inv1 : inv0;
#pragma unroll
        for (int j = 0; j < 8; ++j)
#pragma unroll
            for (int e2 = 0; e2 < 2; ++e2) {
                int vc = j * 8 + (lane & 3) * 2 + e2;
                float re = accR[j][2 * t + e2] * inv;
                float im = accI[j][2 * t + e2] * inv;
                __half* p = g_Aatt + r * GK + (h * 64 + vc);
                p[0] = __float2half(re);
                p[1024] = __float2half(im);
                p[2048] = __float2half(re + im);
            }
    }
}

// ---------------------------------------------------------------------------
extern "C" void kernel_launch(void* const* d_in, const int* in_sizes, int n_in,
                              void* d_out, int out_size)
{
    const float* xre = (const float*)d_in[0];
    const float* xim = (const float*)d_in[1];
    float* out = (float*)d_out;

    const int gemm_smem = 2 * STAGEB;                 // 55296 per CTA (2 CTAs/SM)
    static bool attr_set = false;
    if (!attr_set) {
        cudaFuncSetAttribute(gemm_hmma,
                             cudaFuncAttributeMaxDynamicSharedMemorySize, gemm_smem);
        cudaFuncSetAttribute(attn_mma,
                             cudaFuncAttributeMaxDynamicSharedMemorySize, AT_TOT);
        attr_set = true;
    }

    pack_A_proj<<<16384, 256>>>(xre, xim);
    pack_B_proj<<<20480, 256>>>((const float*)d_in[2], (const float*)d_in[3],
                                (const float*)d_in[4], (const float*)d_in[5],
                                (const float*)d_in[6], (const float*)d_in[7]);
    pack_B_out<<<4096, 256>>>((const float*)d_in[8], (const float*)d_in[9]);

    gemm_hmma<<<dim3(32, 80), 256, gemm_smem>>>(0, nullptr, nullptr, nullptr);

    attn_mma<<<dim3(16, 64), 128, AT_TOT>>>();

    gemm_hmma<<<dim3(32, 16), 256, gemm_smem>>>(1, out, xre, xim);
}

// round 14
// speedup vs baseline: 1.0406x; 1.0179x over previous
#include <cuda_runtime.h>
#include <cuda_fp16.h>
#include <cstdint>
#include <math.h>

#define Ssz 1024
#define Bsz 4
#define Esz 1024
#define SBE (Ssz * Bsz * Esz)
#define GK  3072                    // 3 planes x 1024 (Gauss: ar | ai | ar+ai)
#define NCHUNK 48                   // 48 chunks of 64 (16 per product phase)

// ---------------- scratch -----------------------------------------------------
__device__ __align__(16) __half g_Aproj[4096u * GK];
__device__ __align__(16) __half g_Bproj[5120u * GK];
__device__ __align__(16) __half g_Bout [1024u * GK];
__device__ __align__(16) __half g_Aatt [4096u * GK];
__device__ __align__(16) __half g_qp[64u * 1024 * 256]; // [bh][s][qr(128)|qi(128)]
__device__ __align__(16) __half g_kp[64u * 1024 * 256]; // [bh][t][kr|ki]
__device__ __align__(16) __half g_vt[64u * 128 * 1024]; // [bh][vr(64)|vi(64) planes][t]

// ---------------- helpers ------------------------------------------------------
__device__ __forceinline__ uint32_t smem_u32(const void* p) {
    uint32_t a;
    asm("{ .reg .u64 t; cvta.to.shared.u64 t, %1; cvt.u32.u64 %0, t; }" : "=r"(a) : "l"(p));
    return a;
}
__device__ __forceinline__ void cp_async16(uint32_t dst, const void* src) {
    asm volatile("cp.async.cg.shared.global [%0], [%1], 16;" :: "r"(dst), "l"(src) : "memory");
}
#define CP_COMMIT() asm volatile("cp.async.commit_group;" ::: "memory")
#define CP_WAIT0()  asm volatile("cp.async.wait_group 0;" ::: "memory")
#define CP_WAIT1()  asm volatile("cp.async.wait_group 1;" ::: "memory")
#define CP_WAIT2()  asm volatile("cp.async.wait_group 2;" ::: "memory")

__device__ __forceinline__ void ldsm_x4(uint32_t& r0, uint32_t& r1,
                                        uint32_t& r2, uint32_t& r3, uint32_t a) {
    asm volatile("ldmatrix.sync.aligned.m8n8.x4.shared.b16 {%0,%1,%2,%3}, [%4];"
                 : "=r"(r0), "=r"(r1), "=r"(r2), "=r"(r3) : "r"(a));
}
__device__ __forceinline__ void mma_f16(float* d, const uint32_t* a,
                                        uint32_t b0, uint32_t b1) {
    asm volatile(
        "mma.sync.aligned.m16n8k16.row.col.f32.f16.f16.f32 "
        "{%0,%1,%2,%3}, {%4,%5,%6,%7}, {%8,%9}, {%0,%1,%2,%3};"
        : "+f"(d[0]), "+f"(d[1]), "+f"(d[2]), "+f"(d[3])
        : "r"(a[0]), "r"(a[1]), "r"(a[2]), "r"(a[3]), "r"(b0), "r"(b1));
}
__device__ __forceinline__ uint32_t pack_h2(float lo, float hi) {
    uint32_t r;
    asm("cvt.rn.f16x2.f32 %0, %1, %2;" : "=r"(r) : "f"(hi), "f"(lo));
    return r;
}
// e^x for x <= ~0, FMA-pipe only (no MUFU)
__device__ __forceinline__ float fexp(float x) {
    float t = fmaxf(x * 1.4426950408889634f, -126.0f);
    int k = __float2int_rn(t);
    float f = (t - (float)k) * 0.6931471805599453f;
    float p = 1.0f + f * (1.0f + f * (0.5f + f * (0.16666667f +
                   f * (0.041666667f + f * 0.0083333333f))));
    return p * __int_as_float((k + 127) << 23);
}
// sqrt(re^2+im^2) via bit-hack rsqrt + 2 Newton iters (no MUFU)
__device__ __forceinline__ float famp(float re, float im) {
    float z = fmaf(re, re, im * im);
    z = fmaxf(z, 1e-37f);
    float r = __int_as_float(0x5f3759df - (__float_as_int(z) >> 1));
    r = r * fmaf(-0.5f * z * r, r, 1.5f);
    r = r * fmaf(-0.5f * z * r, r, 1.5f);
    return z * r;
}

// ---------------- pack kernels --------------------------------------------------
__global__ __launch_bounds__(256) void pack_A_proj(
    const float* __restrict__ xre, const float* __restrict__ xim)
{
    int idx = blockIdx.x * 256 + threadIdx.x;
    int r = idx >> 10, e = idx & 1023;
    float ar = xre[idx], ai = xim[idx];
    __half* p = g_Aproj + (size_t)r * GK + e;
    p[0] = __float2half(ar);
    p[1024] = __float2half(ai);
    p[2048] = __float2half(ar + ai);
}

// Gauss B row: [br | bi | br+bi]
__device__ __forceinline__ void write_B_row(__half* base, size_t row,
                                            int e, float wr, float wi)
{
    __half* p = base + row * GK + e;
    p[0] = __float2half(wr);
    p[1024] = __float2half(wi);
    p[2048] = __float2half(wr + wi);
}

__global__ __launch_bounds__(256) void pack_B_proj(
    const float* __restrict__ wq_re, const float* __restrict__ wq_im,
    const float* __restrict__ wk_re, const float* __restrict__ wk_im,
    const float* __restrict__ wv_re, const float* __restrict__ wv_im)
{
    int idx = blockIdx.x * 256 + threadIdx.x;
    int c = idx >> 10, e = idx & 1023;
    const float *wre, *wim; size_t off;
    if (c < 2048)      { wre = wq_re; wim = wq_im; off = (size_t)c * 1024 + e; }
    else if (c < 4096) { wre = wk_re; wim = wk_im; off = (size_t)(c - 2048) * 1024 + e; }
    else               { wre = wv_re; wim = wv_im; off = (size_t)(c - 4096) * 1024 + e; }
    write_B_row(g_Bproj, (size_t)c, e, wre[off], wim[off]);
}

__global__ __launch_bounds__(256) void pack_B_out(
    const float* __restrict__ wo_re, const float* __restrict__ wo_im)
{
    int idx = blockIdx.x * 256 + threadIdx.x;
    int f = idx >> 10, e = idx & 1023;
    write_B_row(g_Bout, (size_t)f, e,
                wo_re[(size_t)e * 1024 + f], wo_im[(size_t)e * 1024 + f]);
}

// ------ Gauss HMMA GEMM (128 rows x 64 complex cols, K-chunk 64, 4-stage, 2 CTA/SM)
#define ROWB   144                  // 64 fp16 = 128B data + 16B pad
#define STAGEB (192 * ROWB)         // 27648: A(128 rows) + B(64 rows)
#define BOFF   (128 * ROWB)

__device__ __forceinline__ void load_stage(
    uint32_t smb, int stage, const __half* A, const __half* B,
    int rowBase, int colBase, int kk, int tid)
{
    uint32_t base = smb + stage * STAGEB;
#pragma unroll
    for (int i = 0; i < 4; ++i) {   // A: 128 rows x 8 segs
        int v = tid + i * 256, row = v >> 3, seg = v & 7;
        cp_async16(base + row * ROWB + seg * 16,
                   A + (size_t)(rowBase + row) * GK + kk + seg * 8);
    }
#pragma unroll
    for (int i = 0; i < 2; ++i) {   // B: 64 rows x 8 segs
        int v = tid + i * 256, row = v >> 3, seg = v & 7;
        cp_async16(base + BOFF + row * ROWB + seg * 16,
                   B + (size_t)(colBase + row) * GK + kk + seg * 8);
    }
}

__global__ __launch_bounds__(256, 2) void gemm_hmma(
    int mode, float* __restrict__ Dout,
    const float* __restrict__ xre, const float* __restrict__ xim)
{
    extern __shared__ char sm[];
    const uint32_t smb = smem_u32(sm);
    const int tid = threadIdx.x;
    const int wid = tid >> 5, lane = tid & 31;
    const int warpM = wid >> 1, warpN = wid & 1;      // 4M x 2N, warp 32 x 32c
    const int rowBase = blockIdx.x * 128;
    const int colBase = blockIdx.y * 64;              // complex cols
    const __half* A = mode ? g_Aatt : g_Aproj;
    const __half* B = mode ? g_Bout : g_Bproj;

    float accP[3][2][4][4];                           // P1,P2,P3
#pragma unroll
    for (int p = 0; p < 3; ++p)
#pragma unroll
        for (int i = 0; i < 2; ++i)
#pragma unroll
            for (int j = 0; j < 4; ++j)
#pragma unroll
                for (int k = 0; k < 4; ++k) accP[p][i][j][k] = 0.f;

    load_stage(smb, 0, A, B, rowBase, colBase, 0, tid);   CP_COMMIT();
    load_stage(smb, 1, A, B, rowBase, colBase, 64, tid);  CP_COMMIT();
    load_stage(smb, 2, A, B, rowBase, colBase, 128, tid); CP_COMMIT();

    const uint32_t aRowAddr = smb + (warpM * 32 + (lane & 15)) * ROWB + (lane >> 4) * 16;
    const uint32_t bRowAddr = smb + BOFF + (warpN * 32 + (lane & 15)) * ROWB + (lane >> 4) * 16;

#pragma unroll
    for (int ph = 0; ph < 3; ++ph) {
#pragma unroll 1
        for (int c2 = 0; c2 < 16; ++c2) {
            const int c = ph * 16 + c2;
            CP_WAIT2();              // chunks c+1, c+2 may still be in flight
            __syncthreads();         // also releases buffer (c+3)&3 (read at c-1)
            if (c + 3 < NCHUNK)
                load_stage(smb, (c + 3) & 3, A, B, rowBase, colBase, (c + 3) * 64, tid);
            CP_COMMIT();
            const uint32_t stoff = (c & 3) * STAGEB;
#pragma unroll
            for (int ks = 0; ks < 4; ++ks) {
                uint32_t a[2][4], b[4][2];
#pragma unroll
                for (int i = 0; i < 2; ++i)
                    ldsm_x4(a[i][0], a[i][1], a[i][2], a[i][3],
                            aRowAddr + stoff + i * 16 * ROWB + ks * 32);
#pragma unroll
                for (int jj = 0; jj < 2; ++jj) {
                    uint32_t r0, r1, r2, r3;
                    ldsm_x4(r0, r1, r2, r3, bRowAddr + stoff + jj * 16 * ROWB + ks * 32);
                    b[2 * jj][0] = r0; b[2 * jj][1] = r2;
                    b[2 * jj + 1][0] = r1; b[2 * jj + 1][1] = r3;
                }
#pragma unroll
                for (int i = 0; i < 2; ++i)
#pragma unroll
                    for (int j = 0; j < 4; ++j)
                        mma_f16(accP[ph][i][j], a[i], b[j][0], b[j][1]);
            }
        }
    }

    const int lrow = lane >> 2;
#pragma unroll
    for (int i = 0; i < 2; ++i) {
        int r0 = rowBase + warpM * 32 + i * 16 + lrow;
#pragma unroll
        for (int j = 0; j < 4; ++j) {
            int ccc = colBase + warpN * 32 + j * 8 + (lane & 3) * 2;
#pragma unroll
            for (int t = 0; t < 2; ++t) {
                int r = r0 + t * 8;
#pragma unroll
                for (int e2 = 0; e2 < 2; ++e2) {
                    int q = 2 * t + e2;
                    float P1 = accP[0][i][j][q];
                    float P2 = accP[1][i][j][q];
                    float P3 = accP[2][i][j][q];
                    float vre = P1 - P2;
                    float vim = P3 - P1 - P2;
                    int cc = ccc + e2;
                    if (mode == 0) {
                        int s = r >> 2, bb = r & 3;
                        if (cc < 2048) {
                            int h = cc >> 7, m = cc & 127;
                            __half* d = g_qp + ((size_t)(bb * 16 + h) * 1024 + s) * 256;
                            d[m] = __float2half(vre); d[128 + m] = __float2half(vim);
                        } else if (cc < 4096) {
                            int u = cc - 2048, h = u >> 7, m = u & 127;
                            __half* d = g_kp + ((size_t)(bb * 16 + h) * 1024 + s) * 256;
                            d[m] = __float2half(vre); d[128 + m] = __float2half(vim);
                        } else {
                            int u = cc - 4096, h = u >> 6, vc = u & 63;
                            __half* d = g_vt + (size_t)(bb * 16 + h) * 128 * 1024;
                            d[(size_t)vc * 1024 + s]        = __float2half(vre);
                            d[(size_t)(64 + vc) * 1024 + s] = __float2half(vim);
                        }
                    } else {
                        size_t i0 = (size_t)r * 1024 + cc;
                        Dout[i0]       = vre + xre[i0];
                        Dout[SBE + i0] = vim + xim[i0];
                    }
                }
            }
        }
    }
}

// ---------------- HMMA flash attention (unchanged) -------------------------------
#define QPITCH 528
#define KPITCH 528
#define VPITCH 80
#define AT_SMK0 (64 * QPITCH)
#define AT_SMK1 (AT_SMK0 + 32 * KPITCH)
#define AT_SMV0 (AT_SMK1 + 32 * KPITCH)
#define AT_SMV1 (AT_SMV0 + 128 * VPITCH)
#define AT_TOT  (AT_SMV1 + 128 * VPITCH)

__device__ __forceinline__ void load_kv(uint32_t smb, int buf,
    const __half* Kg, const __half* Vg, int kt, int tid)
{
    uint32_t kdst = smb + (buf ? AT_SMK1 : AT_SMK0);
    const __half* ksrc = Kg + (size_t)kt * 32 * 256;
#pragma unroll
    for (int i = 0; i < 8; ++i) {
        int c = tid + i * 128, row = c >> 5, seg = c & 31;
        cp_async16(kdst + row * KPITCH + seg * 16, ksrc + (size_t)row * 256 + seg * 8);
    }
    uint32_t vdst = smb + (buf ? AT_SMV1 : AT_SMV0);
#pragma unroll
    for (int i = 0; i < 4; ++i) {
        int c = tid + i * 128, vc = c >> 2, seg = c & 3;
        cp_async16(vdst + vc * VPITCH + seg * 16,
                   Vg + (size_t)vc * 1024 + kt * 32 + seg * 8);
    }
}

__global__ __launch_bounds__(128) void attn_mma()
{
    extern __shared__ char sm[];
    const uint32_t smb = smem_u32(sm);
    const int tid = threadIdx.x, lane = tid & 31, wid = tid >> 5;
    const int qt = 15 - blockIdx.x;
    const int bh = blockIdx.y;
    const int qbase = qt * 64;
    const int nkt = 2 * qt + 2;
    const float scale = 0.088388347648318447f;

    const __half* Qg = g_qp + ((size_t)bh * 1024 + qbase) * 256;
    const __half* Kg = g_kp + (size_t)bh * 1024 * 256;
    const __half* Vg = g_vt + (size_t)bh * 128 * 1024;

#pragma unroll
    for (int i = 0; i < 16; ++i) {
        int c = tid + i * 128, row = c >> 5, seg = c & 31;
        cp_async16(smb + row * QPITCH + seg * 16, Qg + (size_t)row * 256 + seg * 8);
    }
    load_kv(smb, 0, Kg, Vg, 0, tid);
    CP_COMMIT();

    float m0 = -1e30f, m1 = -1e30f, l0 = 0.f, l1 = 0.f;
    float accR[8][4], accI[8][4];
#pragma unroll
    for (int j = 0; j < 8; ++j)
#pragma unroll
        for (int k = 0; k < 4; ++k) { accR[j][k] = 0.f; accI[j][k] = 0.f; }

    const int rowg = qbase + wid * 16 + (lane >> 2);
    const uint32_t aBase = smb + (wid * 16 + (lane & 15)) * QPITCH + (lane >> 4) * 16;

#pragma unroll 1
    for (int kt = 0; kt < nkt; ++kt) {
        if (kt + 1 < nkt) { load_kv(smb, (kt + 1) & 1, Kg, Vg, kt + 1, tid); CP_COMMIT(); CP_WAIT1(); }
        else CP_WAIT0();
        __syncthreads();
        const uint32_t kbuf = smb + ((kt & 1) ? AT_SMK1 : AT_SMK0);
        const uint32_t vbuf = smb + ((kt & 1) ? AT_SMV1 : AT_SMV0);

        float S[4][4][4];
#pragma unroll
        for (int c2 = 0; c2 < 4; ++c2)
#pragma unroll
            for (int n = 0; n < 4; ++n)
#pragma unroll
                for (int q = 0; q < 4; ++q) S[c2][n][q] = 0.f;

#pragma unroll
        for (int ks = 0; ks < 8; ++ks) {
            uint32_t ar[4], ai[4];
            uint32_t aa = aBase + ks * 32;
            ldsm_x4(ar[0], ar[1], ar[2], ar[3], aa);
            ldsm_x4(ai[0], ai[1], ai[2], ai[3], aa + 256);
#pragma unroll
            for (int ntp = 0; ntp < 2; ++ntp) {
                uint32_t ba = kbuf + (ntp * 16 + (lane & 15)) * KPITCH + (lane >> 4) * 16 + ks * 32;
                uint32_t br[4], bi[4];
                ldsm_x4(br[0], br[1], br[2], br[3], ba);
                ldsm_x4(bi[0], bi[1], bi[2], bi[3], ba + 256);
#pragma unroll
                for (int t2 = 0; t2 < 2; ++t2) {
                    int nt = 2 * ntp + t2;
                    mma_f16(S[0][nt], ar, br[t2], br[t2 + 2]);
                    mma_f16(S[1][nt], ai, bi[t2], bi[t2 + 2]);
                    mma_f16(S[2][nt], ar, bi[t2], bi[t2 + 2]);
                    mma_f16(S[3][nt], ai, br[t2], br[t2 + 2]);
                }
            }
        }

        float mx0 = -1e30f, mx1 = -1e30f;
#pragma unroll
        for (int nt = 0; nt < 4; ++nt)
#pragma unroll
            for (int q = 0; q < 4; ++q) {
                float re = S[0][nt][q] - S[1][nt][q];
                float im = S[2][nt][q] + S[3][nt][q];
                float amp = famp(re, im) * scale;
                int col = kt * 32 + nt * 8 + (lane & 3) * 2 + (q & 1);
                int row = rowg + ((q >> 1) ? 8 : 0);
                float logit = (col <= row) ? amp : -1e30f;
                S[0][nt][q] = logit;
                if (q < 2) mx0 = fmaxf(mx0, logit);
                else       mx1 = fmaxf(mx1, logit);
            }
        mx0 = fmaxf(mx0, __shfl_xor_sync(~0u, mx0, 1));
        mx0 = fmaxf(mx0, __shfl_xor_sync(~0u, mx0, 2));
        mx1 = fmaxf(mx1, __shfl_xor_sync(~0u, mx1, 1));
        mx1 = fmaxf(mx1, __shfl_xor_sync(~0u, mx1, 2));
        float m0n = fmaxf(m0, mx0), m1n = fmaxf(m1, mx1);
        float corr0 = fexp(m0 - m0n), corr1 = fexp(m1 - m1n);
        float ph[4][4];
        float sum0 = 0.f, sum1 = 0.f;
#pragma unroll
        for (int nt = 0; nt < 4; ++nt)
#pragma unroll
            for (int q = 0; q < 4; ++q) {
                float p = fexp(S[0][nt][q] - ((q < 2) ? m0n : m1n));
                if (q < 2) sum0 += p; else sum1 += p;
                ph[nt][q] = p;
            }
        sum0 += __shfl_xor_sync(~0u, sum0, 1);
        sum0 += __shfl_xor_sync(~0u, sum0, 2);
        sum1 += __shfl_xor_sync(~0u, sum1, 1);
        sum1 += __shfl_xor_sync(~0u, sum1, 2);
        l0 = l0 * corr0 + sum0;
        l1 = l1 * corr1 + sum1;
        m0 = m0n; m1 = m1n;
#pragma unroll
        for (int j = 0; j < 8; ++j) {
            accR[j][0] *= corr0; accR[j][1] *= corr0;
            accR[j][2] *= corr1; accR[j][3] *= corr1;
            accI[j][0] *= corr0; accI[j][1] *= corr0;
            accI[j][2] *= corr1; accI[j][3] *= corr1;
        }

#pragma unroll
        for (int s = 0; s < 2; ++s) {
            uint32_t Ah[4];
            Ah[0] = pack_h2(ph[2 * s][0], ph[2 * s][1]);
            Ah[1] = pack_h2(ph[2 * s][2], ph[2 * s][3]);
            Ah[2] = pack_h2(ph[2 * s + 1][0], ph[2 * s + 1][1]);
            Ah[3] = pack_h2(ph[2 * s + 1][2], ph[2 * s + 1][3]);
#pragma unroll
            for (int pr = 0; pr < 4; ++pr) {
                uint32_t va = vbuf + (pr * 16 + (lane & 15)) * VPITCH + (lane >> 4) * 16 + s * 32;
                uint32_t vr[4], vi[4];
                ldsm_x4(vr[0], vr[1], vr[2], vr[3], va);
                ldsm_x4(vi[0], vi[1], vi[2], vi[3], va + 64 * VPITCH);
                mma_f16(accR[2 * pr],     Ah, vr[0], vr[2]);
                mma_f16(accR[2 * pr + 1], Ah, vr[1], vr[3]);
                mma_f16(accI[2 * pr],     Ah, vi[0], vi[2]);
                mma_f16(accI[2 * pr + 1], Ah, vi[1], vi[3]);
            }
        }
        __syncthreads();
    }

    // epilogue: write Gauss-packed A rows for the out-GEMM
    const float inv0 = 1.0f / l0, inv1 = 1.0f / l1;
    const int b = bh >> 4, h = bh & 15;
#pragma unroll
    for (int t = 0; t < 2; ++t) {
        int srow = rowg + t * 8;
        size_t r = (size_t)srow * 4 + b;
        float inv = t ? inv1 : inv0;
#pragma unroll
        for (int j = 0; j < 8; ++j)
#pragma unroll
            for (int e2 = 0; e2 < 2; ++e2) {
                int vc = j * 8 + (lane & 3) * 2 + e2;
                float re = accR[j][2 * t + e2] * inv;
                float im = accI[j][2 * t + e2] * inv;
                __half* p = g_Aatt + r * GK + (h * 64 + vc);
                p[0] = __float2half(re);
                p[1024] = __float2half(im);
                p[2048] = __float2half(re + im);
            }
    }
}

// ---------------------------------------------------------------------------
extern "C" void kernel_launch(void* const* d_in, const int* in_sizes, int n_in,
                              void* d_out, int out_size)
{
    const float* xre = (const float*)d_in[0];
    const float* xim = (const float*)d_in[1];
    float* out = (float*)d_out;

    const int gemm_smem = 4 * STAGEB;                 // 110592 per CTA (2 CTAs/SM)
    static bool attr_set = false;
    if (!attr_set) {
        cudaFuncSetAttribute(gemm_hmma,
                             cudaFuncAttributeMaxDynamicSharedMemorySize, gemm_smem);
        cudaFuncSetAttribute(attn_mma,
                             cudaFuncAttributeMaxDynamicSharedMemorySize, AT_TOT);
        attr_set = true;
    }

    pack_A_proj<<<16384, 256>>>(xre, xim);
    pack_B_proj<<<20480, 256>>>((const float*)d_in[2], (const float*)d_in[3],
                                (const float*)d_in[4], (const float*)d_in[5],
                                (const float*)d_in[6], (const float*)d_in[7]);
    pack_B_out<<<4096, 256>>>((const float*)d_in[8], (const float*)d_in[9]);

    gemm_hmma<<<dim3(32, 80), 256, gemm_smem>>>(0, nullptr, nullptr, nullptr);

    attn_mma<<<dim3(16, 64), 128, AT_TOT>>>();

    gemm_hmma<<<dim3(32, 16), 256, gemm_smem>>>(1, out, xre, xim);
}

// round 15
// speedup vs baseline: 1.0433x; 1.0026x over previous
#include <cuda_runtime.h>
#include <cuda_fp16.h>
#include <cstdint>
#include <math.h>

#define Ssz 1024
#define Bsz 4
#define Esz 1024
#define SBE (Ssz * Bsz * Esz)
#define GK  3072                    // 3 planes x 1024 (Gauss: ar | ai | ar+ai)
#define NCHUNK 48                   // 48 chunks of 64 (16 per product phase)

// ---------------- scratch -----------------------------------------------------
__device__ __align__(16) __half g_Aproj[4096u * GK];
__device__ __align__(16) __half g_Bproj[5120u * GK];
__device__ __align__(16) __half g_Bout [1024u * GK];
__device__ __align__(16) __half g_Aatt [4096u * GK];
__device__ __align__(16) __half g_qp[64u * 1024 * 256]; // [bh][s][qr(128)|qi(128)]
__device__ __align__(16) __half g_kp[64u * 1024 * 256]; // [bh][t][kr|ki]
__device__ __align__(16) __half g_vt[64u * 128 * 1024]; // [bh][vr(64)|vi(64) planes][t]

// ---------------- helpers ------------------------------------------------------
__device__ __forceinline__ uint32_t smem_u32(const void* p) {
    uint32_t a;
    asm("{ .reg .u64 t; cvta.to.shared.u64 t, %1; cvt.u32.u64 %0, t; }" : "=r"(a) : "l"(p));
    return a;
}
__device__ __forceinline__ void cp_async16(uint32_t dst, const void* src) {
    asm volatile("cp.async.cg.shared.global [%0], [%1], 16;" :: "r"(dst), "l"(src) : "memory");
}
#define CP_COMMIT() asm volatile("cp.async.commit_group;" ::: "memory")
#define CP_WAIT0()  asm volatile("cp.async.wait_group 0;" ::: "memory")
#define CP_WAIT1()  asm volatile("cp.async.wait_group 1;" ::: "memory")
#define CP_WAIT2()  asm volatile("cp.async.wait_group 2;" ::: "memory")

__device__ __forceinline__ void ldsm_x4(uint32_t& r0, uint32_t& r1,
                                        uint32_t& r2, uint32_t& r3, uint32_t a) {
    asm volatile("ldmatrix.sync.aligned.m8n8.x4.shared.b16 {%0,%1,%2,%3}, [%4];"
                 : "=r"(r0), "=r"(r1), "=r"(r2), "=r"(r3) : "r"(a));
}
__device__ __forceinline__ void mma_f16(float* d, const uint32_t* a,
                                        uint32_t b0, uint32_t b1) {
    asm volatile(
        "mma.sync.aligned.m16n8k16.row.col.f32.f16.f16.f32 "
        "{%0,%1,%2,%3}, {%4,%5,%6,%7}, {%8,%9}, {%0,%1,%2,%3};"
        : "+f"(d[0]), "+f"(d[1]), "+f"(d[2]), "+f"(d[3])
        : "r"(a[0]), "r"(a[1]), "r"(a[2]), "r"(a[3]), "r"(b0), "r"(b1));
}
__device__ __forceinline__ uint32_t pack_h2(float lo, float hi) {
    uint32_t r;
    asm("cvt.rn.f16x2.f32 %0, %1, %2;" : "=r"(r) : "f"(hi), "f"(lo));
    return r;
}
// e^x for x <= ~0, FMA-pipe only (no MUFU)
__device__ __forceinline__ float fexp(float x) {
    float t = fmaxf(x * 1.4426950408889634f, -126.0f);
    int k = __float2int_rn(t);
    float f = (t - (float)k) * 0.6931471805599453f;
    float p = 1.0f + f * (1.0f + f * (0.5f + f * (0.16666667f +
                   f * (0.041666667f + f * 0.0083333333f))));
    return p * __int_as_float((k + 127) << 23);
}
// sqrt(re^2+im^2) via bit-hack rsqrt + 2 Newton iters (no MUFU)
__device__ __forceinline__ float famp(float re, float im) {
    float z = fmaf(re, re, im * im);
    z = fmaxf(z, 1e-37f);
    float r = __int_as_float(0x5f3759df - (__float_as_int(z) >> 1));
    r = r * fmaf(-0.5f * z * r, r, 1.5f);
    r = r * fmaf(-0.5f * z * r, r, 1.5f);
    return z * r;
}

// ---------------- pack kernels --------------------------------------------------
__global__ __launch_bounds__(256) void pack_A_proj(
    const float* __restrict__ xre, const float* __restrict__ xim)
{
    int idx = blockIdx.x * 256 + threadIdx.x;
    int r = idx >> 10, e = idx & 1023;
    float ar = xre[idx], ai = xim[idx];
    __half* p = g_Aproj + (size_t)r * GK + e;
    p[0] = __float2half(ar);
    p[1024] = __float2half(ai);
    p[2048] = __float2half(ar + ai);
}

// Gauss B row: [br | bi | br+bi]
__device__ __forceinline__ void write_B_row(__half* base, size_t row,
                                            int e, float wr, float wi)
{
    __half* p = base + row * GK + e;
    p[0] = __float2half(wr);
    p[1024] = __float2half(wi);
    p[2048] = __float2half(wr + wi);
}

__global__ __launch_bounds__(256) void pack_B_proj(
    const float* __restrict__ wq_re, const float* __restrict__ wq_im,
    const float* __restrict__ wk_re, const float* __restrict__ wk_im,
    const float* __restrict__ wv_re, const float* __restrict__ wv_im)
{
    int idx = blockIdx.x * 256 + threadIdx.x;
    int c = idx >> 10, e = idx & 1023;
    const float *wre, *wim; size_t off;
    if (c < 2048)      { wre = wq_re; wim = wq_im; off = (size_t)c * 1024 + e; }
    else if (c < 4096) { wre = wk_re; wim = wk_im; off = (size_t)(c - 2048) * 1024 + e; }
    else               { wre = wv_re; wim = wv_im; off = (size_t)(c - 4096) * 1024 + e; }
    write_B_row(g_Bproj, (size_t)c, e, wre[off], wim[off]);
}

__global__ __launch_bounds__(256) void pack_B_out(
    const float* __restrict__ wo_re, const float* __restrict__ wo_im)
{
    int idx = blockIdx.x * 256 + threadIdx.x;
    int f = idx >> 10, e = idx & 1023;
    write_B_row(g_Bout, (size_t)f, e,
                wo_re[(size_t)e * 1024 + f], wo_im[(size_t)e * 1024 + f]);
}

// ------ Gauss HMMA GEMM (128 rows x 64 complex cols, K-chunk 64, 4-stage, 2 CTA/SM)
#define ROWB   144                  // 64 fp16 = 128B data + 16B pad
#define STAGEB (192 * ROWB)         // 27648: A(128 rows) + B(64 rows)
#define BOFF   (128 * ROWB)
#define EPITCH 68                   // u32 pitch for mode-0 epilogue staging
#define FPITCH 66                   // float2 pitch for mode-1 epilogue staging

__device__ __forceinline__ void load_stage(
    uint32_t smb, int stage, const __half* A, const __half* B,
    int rowBase, int colBase, int kk, int tid)
{
    uint32_t base = smb + stage * STAGEB;
#pragma unroll
    for (int i = 0; i < 4; ++i) {   // A: 128 rows x 8 segs
        int v = tid + i * 256, row = v >> 3, seg = v & 7;
        cp_async16(base + row * ROWB + seg * 16,
                   A + (size_t)(rowBase + row) * GK + kk + seg * 8);
    }
#pragma unroll
    for (int i = 0; i < 2; ++i) {   // B: 64 rows x 8 segs
        int v = tid + i * 256, row = v >> 3, seg = v & 7;
        cp_async16(base + BOFF + row * ROWB + seg * 16,
                   B + (size_t)(colBase + row) * GK + kk + seg * 8);
    }
}

__global__ __launch_bounds__(256, 2) void gemm_hmma(
    int mode, float* __restrict__ Dout,
    const float* __restrict__ xre, const float* __restrict__ xim)
{
    extern __shared__ char sm[];
    const uint32_t smb = smem_u32(sm);
    const int tid = threadIdx.x;
    const int wid = tid >> 5, lane = tid & 31;
    const int warpM = wid >> 1, warpN = wid & 1;      // 4M x 2N, warp 32 x 32c
    const int rowBase = blockIdx.x * 128;
    const int colBase = blockIdx.y * 64;              // complex cols
    const __half* A = mode ? g_Aatt : g_Aproj;
    const __half* B = mode ? g_Bout : g_Bproj;

    float accP[3][2][4][4];                           // P1,P2,P3
#pragma unroll
    for (int p = 0; p < 3; ++p)
#pragma unroll
        for (int i = 0; i < 2; ++i)
#pragma unroll
            for (int j = 0; j < 4; ++j)
#pragma unroll
                for (int k = 0; k < 4; ++k) accP[p][i][j][k] = 0.f;

    load_stage(smb, 0, A, B, rowBase, colBase, 0, tid);   CP_COMMIT();
    load_stage(smb, 1, A, B, rowBase, colBase, 64, tid);  CP_COMMIT();
    load_stage(smb, 2, A, B, rowBase, colBase, 128, tid); CP_COMMIT();

    const uint32_t aRowAddr = smb + (warpM * 32 + (lane & 15)) * ROWB + (lane >> 4) * 16;
    const uint32_t bRowAddr = smb + BOFF + (warpN * 32 + (lane & 15)) * ROWB + (lane >> 4) * 16;

#pragma unroll
    for (int ph = 0; ph < 3; ++ph) {
#pragma unroll 1
        for (int c2 = 0; c2 < 16; ++c2) {
            const int c = ph * 16 + c2;
            CP_WAIT2();
            __syncthreads();
            if (c + 3 < NCHUNK)
                load_stage(smb, (c + 3) & 3, A, B, rowBase, colBase, (c + 3) * 64, tid);
            CP_COMMIT();
            const uint32_t stoff = (c & 3) * STAGEB;
#pragma unroll
            for (int ks = 0; ks < 4; ++ks) {
                uint32_t a[2][4], b[4][2];
#pragma unroll
                for (int i = 0; i < 2; ++i)
                    ldsm_x4(a[i][0], a[i][1], a[i][2], a[i][3],
                            aRowAddr + stoff + i * 16 * ROWB + ks * 32);
#pragma unroll
                for (int jj = 0; jj < 2; ++jj) {
                    uint32_t r0, r1, r2, r3;
                    ldsm_x4(r0, r1, r2, r3, bRowAddr + stoff + jj * 16 * ROWB + ks * 32);
                    b[2 * jj][0] = r0; b[2 * jj][1] = r2;
                    b[2 * jj + 1][0] = r1; b[2 * jj + 1][1] = r3;
                }
#pragma unroll
                for (int i = 0; i < 2; ++i)
#pragma unroll
                    for (int j = 0; j < 4; ++j)
                        mma_f16(accP[ph][i][j], a[i], b[j][0], b[j][1]);
            }
        }
    }

    // ---- epilogue: combine Gauss products, stage in smem, coalesced writes ----
    CP_WAIT0();
    __syncthreads();          // pipeline smem free for reuse

    const int lrow = lane >> 2;
    if (mode == 0) {
        uint32_t* s32 = (uint32_t*)sm;
#pragma unroll
        for (int i = 0; i < 2; ++i)
#pragma unroll
            for (int j = 0; j < 4; ++j)
#pragma unroll
                for (int t = 0; t < 2; ++t)
#pragma unroll
                    for (int e2 = 0; e2 < 2; ++e2) {
                        int q = 2 * t + e2;
                        float P1 = accP[0][i][j][q];
                        float P2 = accP[1][i][j][q];
                        float P3 = accP[2][i][j][q];
                        float vre = P1 - P2;
                        float vim = P3 - P1 - P2;
                        int lr = warpM * 32 + i * 16 + t * 8 + lrow;
                        int ccl = warpN * 32 + j * 8 + (lane & 3) * 2 + e2;
                        s32[lr * EPITCH + ccl] = pack_h2(vre, vim);
                    }
        __syncthreads();

        if (colBase < 4096) {
            // Q or K region: row-major coalesced writes
            int lr = tid >> 1, seg = (tid & 1) * 32;
            int r = rowBase + lr, s = r >> 2, bb = r & 3;
            int u = (colBase < 2048) ? colBase : (colBase - 2048);
            int h = u >> 7, m0 = (u & 127) + seg;
            __half* base = (colBase < 2048) ? g_qp : g_kp;
            __half* d = base + ((size_t)(bb * 16 + h) * 1024 + s) * 256;
            uint32_t reU[16], imU[16];
#pragma unroll
            for (int k2 = 0; k2 < 16; ++k2) {
                uint32_t w0 = s32[lr * EPITCH + seg + 2 * k2];
                uint32_t w1 = s32[lr * EPITCH + seg + 2 * k2 + 1];
                reU[k2] = __byte_perm(w0, w1, 0x5410);
                imU[k2] = __byte_perm(w0, w1, 0x7632);
            }
#pragma unroll
            for (int q = 0; q < 4; ++q)
                ((uint4*)(d + m0))[q] = make_uint4(reU[4*q], reU[4*q+1], reU[4*q+2], reU[4*q+3]);
#pragma unroll
            for (int q = 0; q < 4; ++q)
                ((uint4*)(d + 128 + m0))[q] = make_uint4(imU[4*q], imU[4*q+1], imU[4*q+2], imU[4*q+3]);
        } else {
            // V region: write along s (32 contiguous per (vc,b))
            int vcl = tid >> 2, bb = tid & 3;
            int h = (colBase - 4096) >> 6;
            int s0 = rowBase >> 2;
            __half* d = g_vt + (size_t)(bb * 16 + h) * 128 * 1024
                             + (size_t)vcl * 1024 + s0;
            uint32_t reU[16], imU[16];
#pragma unroll
            for (int k2 = 0; k2 < 16; ++k2) {
                uint32_t w0 = s32[(8 * k2 + bb) * EPITCH + vcl];
                uint32_t w1 = s32[(8 * k2 + 4 + bb) * EPITCH + vcl];
                reU[k2] = __byte_perm(w0, w1, 0x5410);
                imU[k2] = __byte_perm(w0, w1, 0x7632);
            }
#pragma unroll
            for (int q = 0; q < 4; ++q)
                ((uint4*)d)[q] = make_uint4(reU[4*q], reU[4*q+1], reU[4*q+2], reU[4*q+3]);
#pragma unroll
            for (int q = 0; q < 4; ++q)
                ((uint4*)(d + (size_t)64 * 1024))[q]
                    = make_uint4(imU[4*q], imU[4*q+1], imU[4*q+2], imU[4*q+3]);
        }
    } else {
        float2* sf = (float2*)sm;
#pragma unroll
        for (int i = 0; i < 2; ++i)
#pragma unroll
            for (int j = 0; j < 4; ++j)
#pragma unroll
                for (int t = 0; t < 2; ++t)
#pragma unroll
                    for (int e2 = 0; e2 < 2; ++e2) {
                        int q = 2 * t + e2;
                        float P1 = accP[0][i][j][q];
                        float P2 = accP[1][i][j][q];
                        float P3 = accP[2][i][j][q];
                        int lr = warpM * 32 + i * 16 + t * 8 + lrow;
                        int ccl = warpN * 32 + j * 8 + (lane & 3) * 2 + e2;
                        sf[lr * FPITCH + ccl] = make_float2(P1 - P2, P3 - P1 - P2);
                    }
        __syncthreads();

        int lr = tid >> 1, seg = (tid & 1) * 32;
        int r = rowBase + lr;
        size_t base = (size_t)r * 1024 + colBase + seg;
        float re[32], im[32];
#pragma unroll
        for (int k = 0; k < 32; ++k) {
            float2 v = sf[lr * FPITCH + seg + k];
            re[k] = v.x + xre[base + k];
            im[k] = v.y + xim[base + k];
        }
#pragma unroll
        for (int q = 0; q < 8; ++q)
            ((float4*)(Dout + base))[q] = make_float4(re[4*q], re[4*q+1], re[4*q+2], re[4*q+3]);
#pragma unroll
        for (int q = 0; q < 8; ++q)
            ((float4*)(Dout + SBE + base))[q] = make_float4(im[4*q], im[4*q+1], im[4*q+2], im[4*q+3]);
    }
}

// ---------------- HMMA flash attention (unchanged) -------------------------------
#define QPITCH 528
#define KPITCH 528
#define VPITCH 80
#define AT_SMK0 (64 * QPITCH)
#define AT_SMK1 (AT_SMK0 + 32 * KPITCH)
#define AT_SMV0 (AT_SMK1 + 32 * KPITCH)
#define AT_SMV1 (AT_SMV0 + 128 * VPITCH)
#define AT_TOT  (AT_SMV1 + 128 * VPITCH)

__device__ __forceinline__ void load_kv(uint32_t smb, int buf,
    const __half* Kg, const __half* Vg, int kt, int tid)
{
    uint32_t kdst = smb + (buf ? AT_SMK1 : AT_SMK0);
    const __half* ksrc = Kg + (size_t)kt * 32 * 256;
#pragma unroll
    for (int i = 0; i < 8; ++i) {
        int c = tid + i * 128, row = c >> 5, seg = c & 31;
        cp_async16(kdst + row * KPITCH + seg * 16, ksrc + (size_t)row * 256 + seg * 8);
    }
    uint32_t vdst = smb + (buf ? AT_SMV1 : AT_SMV0);
#pragma unroll
    for (int i = 0; i < 4; ++i) {
        int c = tid + i * 128, vc = c >> 2, seg = c & 3;
        cp_async16(vdst + vc * VPITCH + seg * 16,
                   Vg + (size_t)vc * 1024 + kt * 32 + seg * 8);
    }
}

__global__ __launch_bounds__(128) void attn_mma()
{
    extern __shared__ char sm[];
    const uint32_t smb = smem_u32(sm);
    const int tid = threadIdx.x, lane = tid & 31, wid = tid >> 5;
    const int qt = 15 - blockIdx.x;
    const int bh = blockIdx.y;
    const int qbase = qt * 64;
    const int nkt = 2 * qt + 2;
    const float scale = 0.088388347648318447f;

    const __half* Qg = g_qp + ((size_t)bh * 1024 + qbase) * 256;
    const __half* Kg = g_kp + (size_t)bh * 1024 * 256;
    const __half* Vg = g_vt + (size_t)bh * 128 * 1024;

#pragma unroll
    for (int i = 0; i < 16; ++i) {
        int c = tid + i * 128, row = c >> 5, seg = c & 31;
        cp_async16(smb + row * QPITCH + seg * 16, Qg + (size_t)row * 256 + seg * 8);
    }
    load_kv(smb, 0, Kg, Vg, 0, tid);
    CP_COMMIT();

    float m0 = -1e30f, m1 = -1e30f, l0 = 0.f, l1 = 0.f;
    float accR[8][4], accI[8][4];
#pragma unroll
    for (int j = 0; j < 8; ++j)
#pragma unroll
        for (int k = 0; k < 4; ++k) { accR[j][k] = 0.f; accI[j][k] = 0.f; }

    const int rowg = qbase + wid * 16 + (lane >> 2);
    const uint32_t aBase = smb + (wid * 16 + (lane & 15)) * QPITCH + (lane >> 4) * 16;

#pragma unroll 1
    for (int kt = 0; kt < nkt; ++kt) {
        if (kt + 1 < nkt) { load_kv(smb, (kt + 1) & 1, Kg, Vg, kt + 1, tid); CP_COMMIT(); CP_WAIT1(); }
        else CP_WAIT0();
        __syncthreads();
        const uint32_t kbuf = smb + ((kt & 1) ? AT_SMK1 : AT_SMK0);
        const uint32_t vbuf = smb + ((kt & 1) ? AT_SMV1 : AT_SMV0);

        float S[4][4][4];
#pragma unroll
        for (int c2 = 0; c2 < 4; ++c2)
#pragma unroll
            for (int n = 0; n < 4; ++n)
#pragma unroll
                for (int q = 0; q < 4; ++q) S[c2][n][q] = 0.f;

#pragma unroll
        for (int ks = 0; ks < 8; ++ks) {
            uint32_t ar[4], ai[4];
            uint32_t aa = aBase + ks * 32;
            ldsm_x4(ar[0], ar[1], ar[2], ar[3], aa);
            ldsm_x4(ai[0], ai[1], ai[2], ai[3], aa + 256);
#pragma unroll
            for (int ntp = 0; ntp < 2; ++ntp) {
                uint32_t ba = kbuf + (ntp * 16 + (lane & 15)) * KPITCH + (lane >> 4) * 16 + ks * 32;
                uint32_t br[4], bi[4];
                ldsm_x4(br[0], br[1], br[2], br[3], ba);
                ldsm_x4(bi[0], bi[1], bi[2], bi[3], ba + 256);
#pragma unroll
                for (int t2 = 0; t2 < 2; ++t2) {
                    int nt = 2 * ntp + t2;
                    mma_f16(S[0][nt], ar, br[t2], br[t2 + 2]);
                    mma_f16(S[1][nt], ai, bi[t2], bi[t2 + 2]);
                    mma_f16(S[2][nt], ar, bi[t2], bi[t2 + 2]);
                    mma_f16(S[3][nt], ai, br[t2], br[t2 + 2]);
                }
            }
        }

        float mx0 = -1e30f, mx1 = -1e30f;
#pragma unroll
        for (int nt = 0; nt < 4; ++nt)
#pragma unroll
            for (int q = 0; q < 4; ++q) {
                float re = S[0][nt][q] - S[1][nt][q];
                float im = S[2][nt][q] + S[3][nt][q];
                float amp = famp(re, im) * scale;
                int col = kt * 32 + nt * 8 + (lane & 3) * 2 + (q & 1);
                int row = rowg + ((q >> 1) ? 8 : 0);
                float logit = (col <= row) ? amp : -1e30f;
                S[0][nt][q] = logit;
                if (q < 2) mx0 = fmaxf(mx0, logit);
                else       mx1 = fmaxf(mx1, logit);
            }
        mx0 = fmaxf(mx0, __shfl_xor_sync(~0u, mx0, 1));
        mx0 = fmaxf(mx0, __shfl_xor_sync(~0u, mx0, 2));
        mx1 = fmaxf(mx1, __shfl_xor_sync(~0u, mx1, 1));
        mx1 = fmaxf(mx1, __shfl_xor_sync(~0u, mx1, 2));
        float m0n = fmaxf(m0, mx0), m1n = fmaxf(m1, mx1);
        float corr0 = fexp(m0 - m0n), corr1 = fexp(m1 - m1n);
        float ph[4][4];
        float sum0 = 0.f, sum1 = 0.f;
#pragma unroll
        for (int nt = 0; nt < 4; ++nt)
#pragma unroll
            for (int q = 0; q < 4; ++q) {
                float p = fexp(S[0][nt][q] - ((q < 2) ? m0n : m1n));
                if (q < 2) sum0 += p; else sum1 += p;
                ph[nt][q] = p;
            }
        sum0 += __shfl_xor_sync(~0u, sum0, 1);
        sum0 += __shfl_xor_sync(~0u, sum0, 2);
        sum1 += __shfl_xor_sync(~0u, sum1, 1);
        sum1 += __shfl_xor_sync(~0u, sum1, 2);
        l0 = l0 * corr0 + sum0;
        l1 = l1 * corr1 + sum1;
        m0 = m0n; m1 = m1n;
#pragma unroll
        for (int j = 0; j < 8; ++j) {
            accR[j][0] *= corr0; accR[j][1] *= corr0;
            accR[j][2] *= corr1; accR[j][3] *= corr1;
            accI[j][0] *= corr0; accI[j][1] *= corr0;
            accI[j][2] *= corr1; accI[j][3] *= corr1;
        }

#pragma unroll
        for (int s = 0; s < 2; ++s) {
            uint32_t Ah[4];
            Ah[0] = pack_h2(ph[2 * s][0], ph[2 * s][1]);
            Ah[1] = pack_h2(ph[2 * s][2], ph[2 * s][3]);
            Ah[2] = pack_h2(ph[2 * s + 1][0], ph[2 * s + 1][1]);
            Ah[3] = pack_h2(ph[2 * s + 1][2], ph[2 * s + 1][3]);
#pragma unroll
            for (int pr = 0; pr < 4; ++pr) {
                uint32_t va = vbuf + (pr * 16 + (lane & 15)) * VPITCH + (lane >> 4) * 16 + s * 32;
                uint32_t vr[4], vi[4];
                ldsm_x4(vr[0], vr[1], vr[2], vr[3], va);
                ldsm_x4(vi[0], vi[1], vi[2], vi[3], va + 64 * VPITCH);
                mma_f16(accR[2 * pr],     Ah, vr[0], vr[2]);
                mma_f16(accR[2 * pr + 1], Ah, vr[1], vr[3]);
                mma_f16(accI[2 * pr],     Ah, vi[0], vi[2]);
                mma_f16(accI[2 * pr + 1], Ah, vi[1], vi[3]);
            }
        }
        __syncthreads();
    }

    // epilogue: write Gauss-packed A rows for the out-GEMM
    const float inv0 = 1.0f / l0, inv1 = 1.0f / l1;
    const int b = bh >> 4, h = bh & 15;
#pragma unroll
    for (int t = 0; t < 2; ++t) {
        int srow = rowg + t * 8;
        size_t r = (size_t)srow * 4 + b;
        float inv = t ? inv1 : inv0;
#pragma unroll
        for (int j = 0; j < 8; ++j)
#pragma unroll
            for (int e2 = 0; e2 < 2; ++e2) {
                int vc = j * 8 + (lane & 3) * 2 + e2;
                float re = accR[j][2 * t + e2] * inv;
                float im = accI[j][2 * t + e2] * inv;
                __half* p = g_Aatt + r * GK + (h * 64 + vc);
                p[0] = __float2half(re);
                p[1024] = __float2half(im);
                p[2048] = __float2half(re + im);
            }
    }
}

// ---------------------------------------------------------------------------
extern "C" void kernel_launch(void* const* d_in, const int* in_sizes, int n_in,
                              void* d_out, int out_size)
{
    const float* xre = (const float*)d_in[0];
    const float* xim = (const float*)d_in[1];
    float* out = (float*)d_out;

    const int gemm_smem = 4 * STAGEB;                 // 110592 per CTA (2 CTAs/SM)
    static bool attr_set = false;
    if (!attr_set) {
        cudaFuncSetAttribute(gemm_hmma,
                             cudaFuncAttributeMaxDynamicSharedMemorySize, gemm_smem);
        cudaFuncSetAttribute(attn_mma,
                             cudaFuncAttributeMaxDynamicSharedMemorySize, AT_TOT);
        attr_set = true;
    }

    pack_A_proj<<<16384, 256>>>(xre, xim);
    pack_B_proj<<<20480, 256>>>((const float*)d_in[2], (const float*)d_in[3],
                                (const float*)d_in[4], (const float*)d_in[5],
                                (const float*)d_in[6], (const float*)d_in[7]);
    pack_B_out<<<4096, 256>>>((const float*)d_in[8], (const float*)d_in[9]);

    gemm_hmma<<<dim3(32, 80), 256, gemm_smem>>>(0, nullptr, nullptr, nullptr);

    attn_mma<<<dim3(16, 64), 128, AT_TOT>>>();

    gemm_hmma<<<dim3(32, 16), 256, gemm_smem>>>(1, out, xre, xim);
}

// round 16
// speedup vs baseline: 1.1034x; 1.0577x over previous
#include <cuda_runtime.h>
#include <cuda_fp16.h>
#include <cstdint>
#include <math.h>

#define Ssz 1024
#define Bsz 4
#define Esz 1024
#define SBE (Ssz * Bsz * Esz)
#define GK  3072                    // 3 planes x 1024 (Gauss: ar | ai | ar+ai)
#define NCHUNK 48                   // 48 chunks of 64 (16 per product phase)

// ---------------- scratch -----------------------------------------------------
__device__ __align__(16) __half g_Aproj[4096u * GK];
__device__ __align__(16) __half g_Bproj[5120u * GK];
__device__ __align__(16) __half g_Bout [1024u * GK];
__device__ __align__(16) __half g_Aatt [4096u * GK];
__device__ __align__(16) __half g_qp[64u * 1024 * 256]; // [bh][s][qr(128)|qi(128)]
__device__ __align__(16) __half g_kp[64u * 1024 * 256]; // [bh][t][kr|ki]
__device__ __align__(16) __half g_vt[64u * 128 * 1024]; // [bh][vr(64)|vi(64) planes][t]

// ---------------- helpers ------------------------------------------------------
__device__ __forceinline__ uint32_t smem_u32(const void* p) {
    uint32_t a;
    asm("{ .reg .u64 t; cvta.to.shared.u64 t, %1; cvt.u32.u64 %0, t; }" : "=r"(a) : "l"(p));
    return a;
}
__device__ __forceinline__ void cp_async16(uint32_t dst, const void* src) {
    asm volatile("cp.async.cg.shared.global [%0], [%1], 16;" :: "r"(dst), "l"(src) : "memory");
}
#define CP_COMMIT() asm volatile("cp.async.commit_group;" ::: "memory")
#define CP_WAIT0()  asm volatile("cp.async.wait_group 0;" ::: "memory")
#define CP_WAIT2()  asm volatile("cp.async.wait_group 2;" ::: "memory")

__device__ __forceinline__ void ldsm_x4(uint32_t& r0, uint32_t& r1,
                                        uint32_t& r2, uint32_t& r3, uint32_t a) {
    asm volatile("ldmatrix.sync.aligned.m8n8.x4.shared.b16 {%0,%1,%2,%3}, [%4];"
                 : "=r"(r0), "=r"(r1), "=r"(r2), "=r"(r3) : "r"(a));
}
__device__ __forceinline__ void mma_f16(float* d, const uint32_t* a,
                                        uint32_t b0, uint32_t b1) {
    asm volatile(
        "mma.sync.aligned.m16n8k16.row.col.f32.f16.f16.f32 "
        "{%0,%1,%2,%3}, {%4,%5,%6,%7}, {%8,%9}, {%0,%1,%2,%3};"
        : "+f"(d[0]), "+f"(d[1]), "+f"(d[2]), "+f"(d[3])
        : "r"(a[0]), "r"(a[1]), "r"(a[2]), "r"(a[3]), "r"(b0), "r"(b1));
}
__device__ __forceinline__ uint32_t pack_h2(float lo, float hi) {
    uint32_t r;
    asm("cvt.rn.f16x2.f32 %0, %1, %2;" : "=r"(r) : "f"(hi), "f"(lo));
    return r;
}
__device__ __forceinline__ uint32_t hadd2u(uint32_t a, uint32_t b) {
    __half2 r = __hadd2(*(__half2*)&a, *(__half2*)&b);
    return *(uint32_t*)&r;
}
// e^x for x <= ~0, FMA-pipe only (no MUFU)
__device__ __forceinline__ float fexp(float x) {
    float t = fmaxf(x * 1.4426950408889634f, -126.0f);
    int k = __float2int_rn(t);
    float f = (t - (float)k) * 0.6931471805599453f;
    float p = 1.0f + f * (1.0f + f * (0.5f + f * (0.16666667f +
                   f * (0.041666667f + f * 0.0083333333f))));
    return p * __int_as_float((k + 127) << 23);
}
// sqrt(re^2+im^2) via bit-hack rsqrt + 2 Newton iters (no MUFU)
__device__ __forceinline__ float famp(float re, float im) {
    float z = fmaf(re, re, im * im);
    z = fmaxf(z, 1e-37f);
    float r = __int_as_float(0x5f3759df - (__float_as_int(z) >> 1));
    r = r * fmaf(-0.5f * z * r, r, 1.5f);
    r = r * fmaf(-0.5f * z * r, r, 1.5f);
    return z * r;
}

// ---------------- pack kernels --------------------------------------------------
__global__ __launch_bounds__(256) void pack_A_proj(
    const float* __restrict__ xre, const float* __restrict__ xim)
{
    int idx = blockIdx.x * 256 + threadIdx.x;
    int r = idx >> 10, e = idx & 1023;
    float ar = xre[idx], ai = xim[idx];
    __half* p = g_Aproj + (size_t)r * GK + e;
    p[0] = __float2half(ar);
    p[1024] = __float2half(ai);
    p[2048] = __float2half(ar + ai);
}

// Gauss B row: [br | bi | br+bi]
__device__ __forceinline__ void write_B_row(__half* base, size_t row,
                                            int e, float wr, float wi)
{
    __half* p = base + row * GK + e;
    p[0] = __float2half(wr);
    p[1024] = __float2half(wi);
    p[2048] = __float2half(wr + wi);
}

__global__ __launch_bounds__(256) void pack_B_proj(
    const float* __restrict__ wq_re, const float* __restrict__ wq_im,
    const float* __restrict__ wk_re, const float* __restrict__ wk_im,
    const float* __restrict__ wv_re, const float* __restrict__ wv_im)
{
    int idx = blockIdx.x * 256 + threadIdx.x;
    int c = idx >> 10, e = idx & 1023;
    const float *wre, *wim; size_t off;
    if (c < 2048)      { wre = wq_re; wim = wq_im; off = (size_t)c * 1024 + e; }
    else if (c < 4096) { wre = wk_re; wim = wk_im; off = (size_t)(c - 2048) * 1024 + e; }
    else               { wre = wv_re; wim = wv_im; off = (size_t)(c - 4096) * 1024 + e; }
    write_B_row(g_Bproj, (size_t)c, e, wre[off], wim[off]);
}

__global__ __launch_bounds__(256) void pack_B_out(
    const float* __restrict__ wo_re, const float* __restrict__ wo_im)
{
    int idx = blockIdx.x * 256 + threadIdx.x;
    int f = idx >> 10, e = idx & 1023;
    write_B_row(g_Bout, (size_t)f, e,
                wo_re[(size_t)e * 1024 + f], wo_im[(size_t)e * 1024 + f]);
}

// ------ Gauss HMMA GEMM (128 rows x 64 complex cols, K-chunk 64, 4-stage, 2 CTA/SM)
#define ROWB   144
#define STAGEB (192 * ROWB)         // 27648
#define BOFF   (128 * ROWB)
#define EPITCH 68
#define FPITCH 66

__device__ __forceinline__ void load_stage(
    uint32_t smb, int stage, const __half* A, const __half* B,
    int rowBase, int colBase, int kk, int tid)
{
    uint32_t base = smb + stage * STAGEB;
#pragma unroll
    for (int i = 0; i < 4; ++i) {
        int v = tid + i * 256, row = v >> 3, seg = v & 7;
        cp_async16(base + row * ROWB + seg * 16,
                   A + (size_t)(rowBase + row) * GK + kk + seg * 8);
    }
#pragma unroll
    for (int i = 0; i < 2; ++i) {
        int v = tid + i * 256, row = v >> 3, seg = v & 7;
        cp_async16(base + BOFF + row * ROWB + seg * 16,
                   B + (size_t)(colBase + row) * GK + kk + seg * 8);
    }
}

__global__ __launch_bounds__(256, 2) void gemm_hmma(
    int mode, float* __restrict__ Dout,
    const float* __restrict__ xre, const float* __restrict__ xim)
{
    extern __shared__ char sm[];
    const uint32_t smb = smem_u32(sm);
    const int tid = threadIdx.x;
    const int wid = tid >> 5, lane = tid & 31;
    const int warpM = wid >> 1, warpN = wid & 1;
    const int rowBase = blockIdx.x * 128;
    const int colBase = blockIdx.y * 64;
    const __half* A = mode ? g_Aatt : g_Aproj;
    const __half* B = mode ? g_Bout : g_Bproj;

    float accP[3][2][4][4];
#pragma unroll
    for (int p = 0; p < 3; ++p)
#pragma unroll
        for (int i = 0; i < 2; ++i)
#pragma unroll
            for (int j = 0; j < 4; ++j)
#pragma unroll
                for (int k = 0; k < 4; ++k) accP[p][i][j][k] = 0.f;

    load_stage(smb, 0, A, B, rowBase, colBase, 0, tid);   CP_COMMIT();
    load_stage(smb, 1, A, B, rowBase, colBase, 64, tid);  CP_COMMIT();
    load_stage(smb, 2, A, B, rowBase, colBase, 128, tid); CP_COMMIT();

    const uint32_t aRowAddr = smb + (warpM * 32 + (lane & 15)) * ROWB + (lane >> 4) * 16;
    const uint32_t bRowAddr = smb + BOFF + (warpN * 32 + (lane & 15)) * ROWB + (lane >> 4) * 16;

#pragma unroll
    for (int ph = 0; ph < 3; ++ph) {
#pragma unroll 1
        for (int c2 = 0; c2 < 16; ++c2) {
            const int c = ph * 16 + c2;
            CP_WAIT2();
            __syncthreads();
            if (c + 3 < NCHUNK)
                load_stage(smb, (c + 3) & 3, A, B, rowBase, colBase, (c + 3) * 64, tid);
            CP_COMMIT();
            const uint32_t stoff = (c & 3) * STAGEB;
#pragma unroll
            for (int ks = 0; ks < 4; ++ks) {
                uint32_t a[2][4], b[4][2];
#pragma unroll
                for (int i = 0; i < 2; ++i)
                    ldsm_x4(a[i][0], a[i][1], a[i][2], a[i][3],
                            aRowAddr + stoff + i * 16 * ROWB + ks * 32);
#pragma unroll
                for (int jj = 0; jj < 2; ++jj) {
                    uint32_t r0, r1, r2, r3;
                    ldsm_x4(r0, r1, r2, r3, bRowAddr + stoff + jj * 16 * ROWB + ks * 32);
                    b[2 * jj][0] = r0; b[2 * jj][1] = r2;
                    b[2 * jj + 1][0] = r1; b[2 * jj + 1][1] = r3;
                }
#pragma unroll
                for (int i = 0; i < 2; ++i)
#pragma unroll
                    for (int j = 0; j < 4; ++j)
                        mma_f16(accP[ph][i][j], a[i], b[j][0], b[j][1]);
            }
        }
    }

    // ---- epilogue: combine Gauss products, stage in smem, coalesced writes ----
    CP_WAIT0();
    __syncthreads();

    const int lrow = lane >> 2;
    if (mode == 0) {
        uint32_t* s32 = (uint32_t*)sm;
#pragma unroll
        for (int i = 0; i < 2; ++i)
#pragma unroll
            for (int j = 0; j < 4; ++j)
#pragma unroll
                for (int t = 0; t < 2; ++t)
#pragma unroll
                    for (int e2 = 0; e2 < 2; ++e2) {
                        int q = 2 * t + e2;
                        float P1 = accP[0][i][j][q];
                        float P2 = accP[1][i][j][q];
                        float P3 = accP[2][i][j][q];
                        int lr = warpM * 32 + i * 16 + t * 8 + lrow;
                        int ccl = warpN * 32 + j * 8 + (lane & 3) * 2 + e2;
                        s32[lr * EPITCH + ccl] = pack_h2(P1 - P2, P3 - P1 - P2);
                    }
        __syncthreads();

        if (colBase < 4096) {
            int lr = tid >> 1, seg = (tid & 1) * 32;
            int r = rowBase + lr, s = r >> 2, bb = r & 3;
            int u = (colBase < 2048) ? colBase : (colBase - 2048);
            int h = u >> 7, m0 = (u & 127) + seg;
            __half* base = (colBase < 2048) ? g_qp : g_kp;
            __half* d = base + ((size_t)(bb * 16 + h) * 1024 + s) * 256;
            uint32_t reU[16], imU[16];
#pragma unroll
            for (int k2 = 0; k2 < 16; ++k2) {
                uint32_t w0 = s32[lr * EPITCH + seg + 2 * k2];
                uint32_t w1 = s32[lr * EPITCH + seg + 2 * k2 + 1];
                reU[k2] = __byte_perm(w0, w1, 0x5410);
                imU[k2] = __byte_perm(w0, w1, 0x7632);
            }
#pragma unroll
            for (int q = 0; q < 4; ++q)
                ((uint4*)(d + m0))[q] = make_uint4(reU[4*q], reU[4*q+1], reU[4*q+2], reU[4*q+3]);
#pragma unroll
            for (int q = 0; q < 4; ++q)
                ((uint4*)(d + 128 + m0))[q] = make_uint4(imU[4*q], imU[4*q+1], imU[4*q+2], imU[4*q+3]);
        } else {
            int vcl = tid >> 2, bb = tid & 3;
            int h = (colBase - 4096) >> 6;
            int s0 = rowBase >> 2;
            __half* d = g_vt + (size_t)(bb * 16 + h) * 128 * 1024
                             + (size_t)vcl * 1024 + s0;
            uint32_t reU[16], imU[16];
#pragma unroll
            for (int k2 = 0; k2 < 16; ++k2) {
                uint32_t w0 = s32[(8 * k2 + bb) * EPITCH + vcl];
                uint32_t w1 = s32[(8 * k2 + 4 + bb) * EPITCH + vcl];
                reU[k2] = __byte_perm(w0, w1, 0x5410);
                imU[k2] = __byte_perm(w0, w1, 0x7632);
            }
#pragma unroll
            for (int q = 0; q < 4; ++q)
                ((uint4*)d)[q] = make_uint4(reU[4*q], reU[4*q+1], reU[4*q+2], reU[4*q+3]);
#pragma unroll
            for (int q = 0; q < 4; ++q)
                ((uint4*)(d + (size_t)64 * 1024))[q]
                    = make_uint4(imU[4*q], imU[4*q+1], imU[4*q+2], imU[4*q+3]);
        }
    } else {
        float2* sf = (float2*)sm;
#pragma unroll
        for (int i = 0; i < 2; ++i)
#pragma unroll
            for (int j = 0; j < 4; ++j)
#pragma unroll
                for (int t = 0; t < 2; ++t)
#pragma unroll
                    for (int e2 = 0; e2 < 2; ++e2) {
                        int q = 2 * t + e2;
                        float P1 = accP[0][i][j][q];
                        float P2 = accP[1][i][j][q];
                        float P3 = accP[2][i][j][q];
                        int lr = warpM * 32 + i * 16 + t * 8 + lrow;
                        int ccl = warpN * 32 + j * 8 + (lane & 3) * 2 + e2;
                        sf[lr * FPITCH + ccl] = make_float2(P1 - P2, P3 - P1 - P2);
                    }
        __syncthreads();

        int lr = tid >> 1, seg = (tid & 1) * 32;
        int r = rowBase + lr;
        size_t base = (size_t)r * 1024 + colBase + seg;
        float re[32], im[32];
#pragma unroll
        for (int q = 0; q < 8; ++q) {
            float4 xr4 = ((const float4*)(xre + base))[q];
            float4 xi4 = ((const float4*)(xim + base))[q];
            float2 v0 = sf[lr * FPITCH + seg + 4 * q];
            float2 v1 = sf[lr * FPITCH + seg + 4 * q + 1];
            float2 v2 = sf[lr * FPITCH + seg + 4 * q + 2];
            float2 v3 = sf[lr * FPITCH + seg + 4 * q + 3];
            re[4*q] = v0.x + xr4.x; re[4*q+1] = v1.x + xr4.y;
            re[4*q+2] = v2.x + xr4.z; re[4*q+3] = v3.x + xr4.w;
            im[4*q] = v0.y + xi4.x; im[4*q+1] = v1.y + xi4.y;
            im[4*q+2] = v2.y + xi4.z; im[4*q+3] = v3.y + xi4.w;
        }
#pragma unroll
        for (int q = 0; q < 8; ++q)
            ((float4*)(Dout + base))[q] = make_float4(re[4*q], re[4*q+1], re[4*q+2], re[4*q+3]);
#pragma unroll
        for (int q = 0; q < 8; ++q)
            ((float4*)(Dout + SBE + base))[q] = make_float4(im[4*q], im[4*q+1], im[4*q+2], im[4*q+3]);
    }
}

// ---------------- HMMA flash attention (Gauss QK, single-barrier loop) ----------
#define QPITCH 528
#define KPITCH 528
#define VPITCH 80
#define AT_SMK0 (64 * QPITCH)
#define AT_SMK1 (AT_SMK0 + 32 * KPITCH)
#define AT_SMV0 (AT_SMK1 + 32 * KPITCH)
#define AT_SMV1 (AT_SMV0 + 128 * VPITCH)
#define AT_TOT  (AT_SMV1 + 128 * VPITCH)

__device__ __forceinline__ void load_kv(uint32_t smb, int buf,
    const __half* Kg, const __half* Vg, int kt, int tid)
{
    uint32_t kdst = smb + (buf ? AT_SMK1 : AT_SMK0);
    const __half* ksrc = Kg + (size_t)kt * 32 * 256;
#pragma unroll
    for (int i = 0; i < 8; ++i) {
        int c = tid + i * 128, row = c >> 5, seg = c & 31;
        cp_async16(kdst + row * KPITCH + seg * 16, ksrc + (size_t)row * 256 + seg * 8);
    }
    uint32_t vdst = smb + (buf ? AT_SMV1 : AT_SMV0);
#pragma unroll
    for (int i = 0; i < 4; ++i) {
        int c = tid + i * 128, vc = c >> 2, seg = c & 3;
        cp_async16(vdst + vc * VPITCH + seg * 16,
                   Vg + (size_t)vc * 1024 + kt * 32 + seg * 8);
    }
}

__global__ __launch_bounds__(128) void attn_mma()
{
    extern __shared__ char sm[];
    const uint32_t smb = smem_u32(sm);
    const int tid = threadIdx.x, lane = tid & 31, wid = tid >> 5;
    const int qt = 15 - blockIdx.x;
    const int bh = blockIdx.y;
    const int qbase = qt * 64;
    const int nkt = 2 * qt + 2;
    const float scale = 0.088388347648318447f;

    const __half* Qg = g_qp + ((size_t)bh * 1024 + qbase) * 256;
    const __half* Kg = g_kp + (size_t)bh * 1024 * 256;
    const __half* Vg = g_vt + (size_t)bh * 128 * 1024;

#pragma unroll
    for (int i = 0; i < 16; ++i) {
        int c = tid + i * 128, row = c >> 5, seg = c & 31;
        cp_async16(smb + row * QPITCH + seg * 16, Qg + (size_t)row * 256 + seg * 8);
    }
    load_kv(smb, 0, Kg, Vg, 0, tid);
    CP_COMMIT();

    float m0 = -1e30f, m1 = -1e30f, l0 = 0.f, l1 = 0.f;
    float accR[8][4], accI[8][4];
#pragma unroll
    for (int j = 0; j < 8; ++j)
#pragma unroll
        for (int k = 0; k < 4; ++k) { accR[j][k] = 0.f; accI[j][k] = 0.f; }

    const int rowg = qbase + wid * 16 + (lane >> 2);
    const uint32_t aBase = smb + (wid * 16 + (lane & 15)) * QPITCH + (lane >> 4) * 16;

#pragma unroll 1
    for (int kt = 0; kt < nkt; ++kt) {
        CP_WAIT0();
        __syncthreads();           // single barrier: prior reads done, load landed
        if (kt + 1 < nkt) { load_kv(smb, (kt + 1) & 1, Kg, Vg, kt + 1, tid); CP_COMMIT(); }
        const uint32_t kbuf = smb + ((kt & 1) ? AT_SMK1 : AT_SMK0);
        const uint32_t vbuf = smb + ((kt & 1) ? AT_SMV1 : AT_SMV0);

        float S[3][4][4];          // Gauss chains: P1=qr.kr, P2=qi.ki, P3=qs.ks
#pragma unroll
        for (int c2 = 0; c2 < 3; ++c2)
#pragma unroll
            for (int n = 0; n < 4; ++n)
#pragma unroll
                for (int q = 0; q < 4; ++q) S[c2][n][q] = 0.f;

#pragma unroll
        for (int ks = 0; ks < 8; ++ks) {
            uint32_t ar[4], ai[4], as_[4];
            uint32_t aa = aBase + ks * 32;
            ldsm_x4(ar[0], ar[1], ar[2], ar[3], aa);
            ldsm_x4(ai[0], ai[1], ai[2], ai[3], aa + 256);
#pragma unroll
            for (int x = 0; x < 4; ++x) as_[x] = hadd2u(ar[x], ai[x]);
#pragma unroll
            for (int ntp = 0; ntp < 2; ++ntp) {
                uint32_t ba = kbuf + (ntp * 16 + (lane & 15)) * KPITCH + (lane >> 4) * 16 + ks * 32;
                uint32_t br[4], bi[4], bs[4];
                ldsm_x4(br[0], br[1], br[2], br[3], ba);
                ldsm_x4(bi[0], bi[1], bi[2], bi[3], ba + 256);
#pragma unroll
                for (int x = 0; x < 4; ++x) bs[x] = hadd2u(br[x], bi[x]);
#pragma unroll
                for (int t2 = 0; t2 < 2; ++t2) {
                    int nt = 2 * ntp + t2;
                    mma_f16(S[0][nt], ar, br[t2], br[t2 + 2]);
                    mma_f16(S[1][nt], ai, bi[t2], bi[t2 + 2]);
                    mma_f16(S[2][nt], as_, bs[t2], bs[t2 + 2]);
                }
            }
        }

        float mx0 = -1e30f, mx1 = -1e30f;
#pragma unroll
        for (int nt = 0; nt < 4; ++nt)
#pragma unroll
            for (int q = 0; q < 4; ++q) {
                float P1 = S[0][nt][q], P2 = S[1][nt][q], P3 = S[2][nt][q];
                float re = P1 - P2;
                float im = P3 - P1 - P2;
                float amp = famp(re, im) * scale;
                int col = kt * 32 + nt * 8 + (lane & 3) * 2 + (q & 1);
                int row = rowg + ((q >> 1) ? 8 : 0);
                float logit = (col <= row) ? amp : -1e30f;
                S[0][nt][q] = logit;
                if (q < 2) mx0 = fmaxf(mx0, logit);
                else       mx1 = fmaxf(mx1, logit);
            }
        mx0 = fmaxf(mx0, __shfl_xor_sync(~0u, mx0, 1));
        mx0 = fmaxf(mx0, __shfl_xor_sync(~0u, mx0, 2));
        mx1 = fmaxf(mx1, __shfl_xor_sync(~0u, mx1, 1));
        mx1 = fmaxf(mx1, __shfl_xor_sync(~0u, mx1, 2));
        float m0n = fmaxf(m0, mx0), m1n = fmaxf(m1, mx1);
        float corr0 = fexp(m0 - m0n), corr1 = fexp(m1 - m1n);
        float ph[4][4];
        float sum0 = 0.f, sum1 = 0.f;
#pragma unroll
        for (int nt = 0; nt < 4; ++nt)
#pragma unroll
            for (int q = 0; q < 4; ++q) {
                float p = fexp(S[0][nt][q] - ((q < 2) ? m0n : m1n));
                if (q < 2) sum0 += p; else sum1 += p;
                ph[nt][q] = p;
            }
        sum0 += __shfl_xor_sync(~0u, sum0, 1);
        sum0 += __shfl_xor_sync(~0u, sum0, 2);
        sum1 += __shfl_xor_sync(~0u, sum1, 1);
        sum1 += __shfl_xor_sync(~0u, sum1, 2);
        l0 = l0 * corr0 + sum0;
        l1 = l1 * corr1 + sum1;
        m0 = m0n; m1 = m1n;
#pragma unroll
        for (int j = 0; j < 8; ++j) {
            accR[j][0] *= corr0; accR[j][1] *= corr0;
            accR[j][2] *= corr1; accR[j][3] *= corr1;
            accI[j][0] *= corr0; accI[j][1] *= corr0;
            accI[j][2] *= corr1; accI[j][3] *= corr1;
        }

#pragma unroll
        for (int s = 0; s < 2; ++s) {
            uint32_t Ah[4];
            Ah[0] = pack_h2(ph[2 * s][0], ph[2 * s][1]);
            Ah[1] = pack_h2(ph[2 * s][2], ph[2 * s][3]);
            Ah[2] = pack_h2(ph[2 * s + 1][0], ph[2 * s + 1][1]);
            Ah[3] = pack_h2(ph[2 * s + 1][2], ph[2 * s + 1][3]);
#pragma unroll
            for (int pr = 0; pr < 4; ++pr) {
                uint32_t va = vbuf + (pr * 16 + (lane & 15)) * VPITCH + (lane >> 4) * 16 + s * 32;
                uint32_t vr[4], vi[4];
                ldsm_x4(vr[0], vr[1], vr[2], vr[3], va);
                ldsm_x4(vi[0], vi[1], vi[2], vi[3], va + 64 * VPITCH);
                mma_f16(accR[2 * pr],     Ah, vr[0], vr[2]);
                mma_f16(accR[2 * pr + 1], Ah, vr[1], vr[3]);
                mma_f16(accI[2 * pr],     Ah, vi[0], vi[2]);
                mma_f16(accI[2 * pr + 1], Ah, vi[1], vi[3]);
            }
        }
    }

    // epilogue: write Gauss-packed A rows for the out-GEMM
    const float inv0 = 1.0f / l0, inv1 = 1.0f / l1;
    const int b = bh >> 4, h = bh & 15;
#pragma unroll
    for (int t = 0; t < 2; ++t) {
        int srow = rowg + t * 8;
        size_t r = (size_t)srow * 4 + b;
        float inv = t ? inv1 : inv0;
#pragma unroll
        for (int j = 0; j < 8; ++j)
#pragma unroll
            for (int e2 = 0; e2 < 2; ++e2) {
                int vc = j * 8 + (lane & 3) * 2 + e2;
                float re = accR[j][2 * t + e2] * inv;
                float im = accI[j][2 * t + e2] * inv;
                __half* p = g_Aatt + r * GK + (h * 64 + vc);
                p[0] = __float2half(re);
                p[1024] = __float2half(im);
                p[2048] = __float2half(re + im);
            }
    }
}

// ---------------------------------------------------------------------------
extern "C" void kernel_launch(void* const* d_in, const int* in_sizes, int n_in,
                              void* d_out, int out_size)
{
    const float* xre = (const float*)d_in[0];
    const float* xim = (const float*)d_in[1];
    float* out = (float*)d_out;

    const int gemm_smem = 4 * STAGEB;                 // 110592 per CTA (2 CTAs/SM)
    static bool attr_set = false;
    if (!attr_set) {
        cudaFuncSetAttribute(gemm_hmma,
                             cudaFuncAttributeMaxDynamicSharedMemorySize, gemm_smem);
        cudaFuncSetAttribute(attn_mma,
                             cudaFuncAttributeMaxDynamicSharedMemorySize, AT_TOT);
        attr_set = true;
    }

    pack_A_proj<<<16384, 256>>>(xre, xim);
    pack_B_proj<<<20480, 256>>>((const float*)d_in[2], (const float*)d_in[3],
                                (const float*)d_in[4], (const float*)d_in[5],
                                (const float*)d_in[6], (const float*)d_in[7]);
    pack_B_out<<<4096, 256>>>((const float*)d_in[8], (const float*)d_in[9]);

    gemm_hmma<<<dim3(32, 80), 256, gemm_smem>>>(0, nullptr, nullptr, nullptr);

    attn_mma<<<dim3(16, 64), 128, AT_TOT>>>();

    gemm_hmma<<<dim3(32, 16), 256, gemm_smem>>>(1, out, xre, xim);
}